// round 9
// baseline (speedup 1.0000x reference)
#include <cuda_runtime.h>
#include <cstdint>

#define BB 32
#define NN 128
#define NIN 16
#define MHID 64
#define MOUT 64
#define NHID 64
#define NOUT 16
#define KT 4
#define EDGES (NN * (NN - 1))

// Scratch (no cudaMalloc allowed)
__device__ float g_U[BB * NN * KT * MHID];   // [b][n][k][h] sender proj
__device__ float g_V[BB * NN * KT * MHID];   // [b][n][k][h] receiver proj + b1
__device__ float g_W2T[KT * MOUT * MHID];    // W2 transposed [k][m][kk], tf32-rounded
__device__ float g_AGG[BB * NN * MOUT];      // aggregated messages per node

// ---------------- helpers ----------------
__device__ __forceinline__ uint32_t smem_u32(const void* p) {
    uint32_t a;
    asm("{ .reg .u64 t; cvta.to.shared.u64 t, %1; cvt.u32.u64 %0, t; }" : "=r"(a) : "l"(p));
    return a;
}
__device__ __forceinline__ uint32_t f2tf32(float x) {
    uint32_t r; asm("cvt.rna.tf32.f32 %0, %1;" : "=r"(r) : "f"(x)); return r;
}

#if defined(__CUDA_ARCH_FEAT_SM103_ALL)
__device__ __forceinline__ void mma_tf32_ss(uint32_t d, uint64_t a, uint64_t b,
                                            uint32_t idesc, uint32_t en) {
    asm volatile(
        "{\n\t.reg .pred p;\n\tsetp.ne.u32 p, %4, 0;\n\t"
        "tcgen05.mma.cta_group::1.kind::tf32 [%0], %1, %2, %3, {%5, %5, %5, %5}, p;\n\t}\n"
        :: "r"(d), "l"(a), "l"(b), "r"(idesc), "r"(en), "r"(0u) : "memory");
}
#define MBAR_WAIT_PARITY(addr, ph) do {                                          \
    uint32_t _m = (addr), _p = (ph), _done;                                      \
    asm volatile("{\n\t.reg .pred p;\n\t"                                        \
        "mbarrier.try_wait.parity.acquire.cta.shared::cta.b64 p, [%1], %2;\n\t"  \
        "selp.b32 %0, 1, 0, p;\n\t}" : "=r"(_done) : "r"(_m), "r"(_p) : "memory");\
    if (!_done) {                                                                \
        asm volatile("{\n\t.reg .pred P1;\n\t"                                   \
            "WL_%=:\n\t"                                                         \
            "mbarrier.try_wait.parity.acquire.cta.shared::cta.b64 P1, [%0], %1, 0x989680;\n\t" \
            "@P1 bra.uni WD_%=;\n\tbra.uni WL_%=;\n\tWD_%=:\n\t}"                \
            :: "r"(_m), "r"(_p) : "memory");                                     \
    } } while (0)
#define LDTM_X32(r, addr)                                                        \
    asm volatile("tcgen05.ld.sync.aligned.32x32b.x32.b32 "                       \
        "{%0, %1, %2, %3, %4, %5, %6, %7, %8, %9, %10, %11, %12, %13, %14, %15," \
        " %16, %17, %18, %19, %20, %21, %22, %23, %24, %25, %26, %27, %28, %29, %30, %31}, [%32];" \
        : "=r"((r)[0]),  "=r"((r)[1]),  "=r"((r)[2]),  "=r"((r)[3]),             \
          "=r"((r)[4]),  "=r"((r)[5]),  "=r"((r)[6]),  "=r"((r)[7]),             \
          "=r"((r)[8]),  "=r"((r)[9]),  "=r"((r)[10]), "=r"((r)[11]),            \
          "=r"((r)[12]), "=r"((r)[13]), "=r"((r)[14]), "=r"((r)[15]),            \
          "=r"((r)[16]), "=r"((r)[17]), "=r"((r)[18]), "=r"((r)[19]),            \
          "=r"((r)[20]), "=r"((r)[21]), "=r"((r)[22]), "=r"((r)[23]),            \
          "=r"((r)[24]), "=r"((r)[25]), "=r"((r)[26]), "=r"((r)[27]),            \
          "=r"((r)[28]), "=r"((r)[29]), "=r"((r)[30]), "=r"((r)[31])             \
        : "r"(addr))
#define IDESC_TF32 0x08100910u
#define DESC_BASE ((2ull << 61) | (1ull << 46) | (64ull << 32) | (1ull << 16))
__device__ __forceinline__ uint64_t mk_desc(uint32_t addr) {
    return DESC_BASE | ((uint64_t)(addr >> 4) & 0x3FFF);
}
#endif

// decoder dynamic smem layout (from 1024-aligned base)
#define OFF_B     0          // 4 x 16384 = 65536 (W2T, SW128)
#define OFF_A     65536      // 4 x 32768 = 131072 (h1 tiles, SW128)
#define DEC_DYN   (65536 + 131072 + 1024)

// node-MLP kernel smem (float indices)
#define NOFF_W1   0
#define NOFF_W2   5120
#define NOFF_W3   9216
#define NOFF_B    10240
#define NOFF_AUG  10384      // 64*81
#define NOFF_H1   15568      // 64*65
#define NOFF_H2   19728      // 64*65
#define NODE_DYN  (23888 * 4)

// ---------------------------------------------------------------------------
// uv + fused w2t: grid (8, BB), 256 threads, 16 nodes per CTA.
// ---------------------------------------------------------------------------
__global__ __launch_bounds__(256) void uv_kernel(
    const float* __restrict__ inp, const float* __restrict__ W1,
    const float* __restrict__ b1, const float* __restrict__ W2)
{
    const int g = blockIdx.x, b = blockIdx.y;
    const int n0 = g * 16;
    const int t = threadIdx.x;
    const int k = t >> 6, h = t & 63;

    if (b == 0) {
        for (int idx = g * 2048 + t; idx < (g + 1) * 2048; idx += 256) {
            const int kk2 = idx >> 12, rem = idx & 4095, kki = rem >> 6, m = rem & 63;
            ((uint32_t*)g_W2T)[(kk2 * MOUT + m) * MHID + kki] =
                f2tf32(W2[(kk2 * MHID + kki) * MOUT + m]);
        }
    }

    __shared__ float xs[16][NIN];
    {
        const int nn = t & 15, f = t >> 4;
        xs[nn][f] = inp[(b * NIN + f) * NN + n0 + nn];
    }
    __syncthreads();

    const float* w = W1 + k * (2 * NIN) * MHID;
    const float bv = b1[k * MHID + h];
    float u[16], v[16];
#pragma unroll
    for (int nn = 0; nn < 16; nn++) { u[nn] = 0.f; v[nn] = bv; }
#pragma unroll
    for (int f = 0; f < NIN; f++) {
        const float wu = w[f * MHID + h];
        const float wv = w[(NIN + f) * MHID + h];
#pragma unroll
        for (int nn = 0; nn < 16; nn++) {
            u[nn] = fmaf(xs[nn][f], wu, u[nn]);
            v[nn] = fmaf(xs[nn][f], wv, v[nn]);
        }
    }
#pragma unroll
    for (int nn = 0; nn < 16; nn++) {
        g_U[((b * NN + n0 + nn) * KT + k) * MHID + h] = u[nn];
        g_V[((b * NN + n0 + nn) * KT + k) * MHID + h] = v[nn];
    }
}

// ---------------------------------------------------------------------------
// Persistent warp-specialized decoder: grid 148, 512 threads.
//   warps 0-7  (t 0..255)   : A-build + MMA issue, pipelined at k granularity
//   warps 8-15 (t 256..511) : TMEM epilogue + aggregation
// ---------------------------------------------------------------------------
__global__ __launch_bounds__(512, 1) void decoder_kernel(
    const float* __restrict__ rel_types, const float* __restrict__ W2,
    const float* __restrict__ b2)
{
    extern __shared__ char dsm[];
    __shared__ float b2s[KT][MOUT];
    __shared__ float part[8][MOUT];
    __shared__ uint32_t tmem_ptr_s;
    __shared__ __align__(8) uint64_t mbar[3];  // [0]=mma done, [1]=free bank0, [2]=free bank1

    const int t = threadIdx.x;
    const int wid = t >> 5, lane = t & 31;

    const uint32_t dyn = smem_u32(dsm);
    const uint32_t base = (dyn + 1023) & ~1023u;
    char* P = dsm + (base - dyn);

    if (t < 256) b2s[t >> 6][t & 63] = b2[t];

#if defined(__CUDA_ARCH_FEAT_SM103_ALL)
    const uint32_t mb_mma   = smem_u32(&mbar[0]);
    const uint32_t mb_free0 = smem_u32(&mbar[1]);
    const uint32_t mb_free1 = smem_u32(&mbar[2]);

    // stage 4 B tiles (W2T, SW128) once
    for (int idx = t; idx < KT * 64 * 16; idx += 512) {
        const int k = idx >> 10, n = (idx >> 4) & 63, c = (idx & 15) * 4;
        uint4 w4 = *(const uint4*)((const uint32_t*)g_W2T + (k * MOUT + n) * MHID + c);
        uint32_t byte = ((n >> 3) + (c >> 5) * 8) * 1024 + (n & 7) * 128 + (c & 31) * 4;
        byte ^= (byte >> 3) & 0x70;
        *(uint4*)(P + OFF_B + k * 16384 + byte) = w4;
    }
    if (t == 0) {
        asm volatile("mbarrier.init.shared.b64 [%0], 1;" :: "r"(mb_mma) : "memory");
        asm volatile("mbarrier.init.shared.b64 [%0], 1;" :: "r"(mb_free0) : "memory");
        asm volatile("mbarrier.init.shared.b64 [%0], 1;" :: "r"(mb_free1) : "memory");
    }
    if (wid == 0) {
        asm volatile("tcgen05.alloc.cta_group::1.sync.aligned.shared::cta.b32 [%0], %1;"
                     :: "r"(smem_u32(&tmem_ptr_s)), "r"(512u) : "memory");
        asm volatile("tcgen05.relinquish_alloc_permit.cta_group::1.sync.aligned;");
    }
    __syncthreads();
    const uint32_t tmem = tmem_ptr_s;

    if (wid < 8) {
        // ========================= BUILDERS =========================
        // thread constants: col group cg, row group rg; rows rg + 16*it keep
        // r&7 constant so the SW128-swizzled STS address is incremental.
        const int cg = t & 15;           // column group (4 floats)
        const int rg = t >> 4;           // 0..15
        const uint32_t stsoff = ((cg >= 8) ? 16384u : 0u) + (uint32_t)(rg >> 3) * 1024u
                              + (uint32_t)(rg & 7) * 128u
                              + ((uint32_t)((cg & 7) ^ (rg & 7)) << 4);
        const float* ubase = g_U + cg * 4;   // + b*32768 + k*64 + j*256
        const float* vbase = g_V + cg * 4;

        int phB = 0, phF0 = 0, phF1 = 0, tc = 0;
        for (int tile = blockIdx.x; tile < BB * NN; tile += gridDim.x, tc++) {
            const int b = tile >> 7, i = tile & 127;
            const int q = tc & 1;

            // prefetch v_i for all 4 k (before the wait, hides L2 latency)
            float4 vv[KT];
#pragma unroll
            for (int k = 0; k < KT; k++)
                vv[k] = *(const float4*)(vbase + (b * NN + i) * (KT * MHID) + k * MHID);

            if (tc > 0) { MBAR_WAIT_PARITY(mb_mma, phB); phB ^= 1; }  // A free
            if (t == 0 && tc >= 2) {   // TMEM bank-set q free (epilogue tc-2 done)
                if (q == 0) { MBAR_WAIT_PARITY(mb_free0, phF0); phF0 ^= 1; }
                else        { MBAR_WAIT_PARITY(mb_free1, phF1); phF1 ^= 1; }
            }

#pragma unroll
            for (int k = 0; k < KT; k++) {
                // ---- build A_k ----
                const float* us = ubase + b * (NN * KT * MHID) + k * MHID;
                char* sp = P + OFF_A + k * 32768 + stsoff;
#pragma unroll
                for (int it = 0; it < 8; it++, sp += 2048) {
                    const int r = rg + it * 16;
                    uint4 w4 = make_uint4(0u, 0u, 0u, 0u);
                    if (r < NN - 1) {
                        const int j = r + (r >= i);
                        const float4 u = *(const float4*)(us + j * (KT * MHID));
                        w4.x = f2tf32(fmaxf(u.x + vv[k].x, 0.f));
                        w4.y = f2tf32(fmaxf(u.y + vv[k].y, 0.f));
                        w4.z = f2tf32(fmaxf(u.z + vv[k].z, 0.f));
                        w4.w = f2tf32(fmaxf(u.w + vv[k].w, 0.f));
                    }
                    *(uint4*)sp = w4;
                }
                asm volatile("bar.sync 1, 256;" ::: "memory");

                // ---- issue MMA_k (overlaps build of k+1) ----
                if (t == 0) {
                    asm volatile("fence.proxy.async.shared::cta;" ::: "memory");
                    const uint64_t ad = mk_desc(base + OFF_A + k * 32768);
                    const uint64_t bd = mk_desc(base + OFF_B + k * 16384);
                    const uint32_t dcol = tmem + (q * 4 + k) * 64;
#pragma unroll
                    for (int s = 0; s < 8; s++)
                        mma_tf32_ss(dcol,
                                    ad + ((s >> 2) ? 1024u : 0u) + (s & 3) * 2,
                                    bd + ((s >> 2) ? 512u : 0u) + (s & 3) * 2,
                                    IDESC_TF32, (uint32_t)(s > 0));
                    if (k == KT - 1)
                        asm volatile(
                            "tcgen05.commit.cta_group::1.mbarrier::arrive::one.shared::cluster.b64 [%0];"
                            :: "r"(mb_mma) : "memory");
                }
            }
        }
    } else {
        // ========================= EPILOGUE =========================
        const int sub = wid & 3;               // TMEM subpartition
        const int kp = (wid >> 2) & 1;         // k pair: {2kp, 2kp+1}
        const int jrow = sub * 32 + lane;
        const int ewid = wid - 8;

        int phE = 0, tc = 0;
        for (int tile = blockIdx.x; tile < BB * NN; tile += gridDim.x, tc++) {
            const int b = tile >> 7, i = tile & 127;
            const int q = tc & 1;

            float2 rt2 = make_float2(0.f, 0.f);
            if (jrow < NN - 1)
                rt2 = *(const float2*)(rel_types +
                        ((size_t)b * EDGES + (size_t)i * (NN - 1) + jrow) * KT + 2 * kp);

            MBAR_WAIT_PARITY(mb_mma, phE); phE ^= 1;   // MMA(tc) done
            asm volatile("tcgen05.fence::after_thread_sync;" ::: "memory");

#pragma unroll
            for (int chv = 0; chv < 2; chv++) {
                uint32_t d0[32], d1[32];
                LDTM_X32(d0, tmem + (q * 4 + 2 * kp) * 64 + chv * 32);
                LDTM_X32(d1, tmem + (q * 4 + 2 * kp + 1) * 64 + chv * 32);
                asm volatile("tcgen05.wait::ld.sync.aligned;" ::: "memory");
                float a[32];
#pragma unroll
                for (int c = 0; c < 32; c++) {
                    const float v0 = fmaxf(__uint_as_float(d0[c]) + b2s[2 * kp][chv * 32 + c], 0.f);
                    const float v1 = fmaxf(__uint_as_float(d1[c]) + b2s[2 * kp + 1][chv * 32 + c], 0.f);
                    a[c] = rt2.x * v0 + rt2.y * v1;
                }
                // split-butterfly: lane L ends with col L of this 32-col chunk
#pragma unroll
                for (int o = 16; o >= 1; o >>= 1) {
                    const bool up = (lane & o) != 0;
#pragma unroll
                    for (int c = 0; c < 16; c++) {
                        if (c >= o) break;
                        const float send = up ? a[c] : a[c + o];
                        const float keep = up ? a[c + o] : a[c];
                        a[c] = keep + __shfl_xor_sync(0xFFFFFFFFu, send, o);
                    }
                }
                part[ewid][chv * 32 + lane] = a[0];
            }
            asm volatile("tcgen05.fence::before_thread_sync;" ::: "memory");
            asm volatile("bar.sync 2, 256;" ::: "memory");
            if (t == 256) {   // TMEM bank-set q free
                if (q == 0)
                    asm volatile("mbarrier.arrive.shared.b64 _, [%0];" :: "r"(mb_free0) : "memory");
                else
                    asm volatile("mbarrier.arrive.shared.b64 _, [%0];" :: "r"(mb_free1) : "memory");
            }
            {
                const int m = t - 256;
                if (m < 64) {
                    float s = part[0][m];
#pragma unroll
                    for (int w = 1; w < 8; w++) s += part[w][m];
                    g_AGG[(b * NN + i) * MOUT + m] = s;
                }
            }
            asm volatile("bar.sync 2, 256;" ::: "memory");
        }
    }

    __syncthreads();
    if (t == 0) {
        asm volatile("mbarrier.inval.shared.b64 [%0];" :: "r"(mb_mma) : "memory");
        asm volatile("mbarrier.inval.shared.b64 [%0];" :: "r"(mb_free0) : "memory");
        asm volatile("mbarrier.inval.shared.b64 [%0];" :: "r"(mb_free1) : "memory");
    }
    if (wid == 0)
        asm volatile("tcgen05.dealloc.cta_group::1.sync.aligned.b32 %0, %1;"
                     :: "r"(tmem), "r"(512u));
#else
    // ============ SIMT fallback (compile-only for plain sm_103) ============
    __shared__ float vs0[KT][MHID];
    __shared__ float rts0[NN][KT];
    float* h1  = (float*)P;
    float* W2s = (float*)(P + 128 * 68 * 4);

    for (int tile = blockIdx.x; tile < BB * NN; tile += gridDim.x) {
        const int b = tile >> 7, i = tile & 127;
        __syncthreads();
        if (t < 256) vs0[t >> 6][t & 63] = g_V[((b * NN + i) * KT) * MHID + t];
        {
            const float* rtp = rel_types + (size_t)(b * EDGES + i * (NN - 1)) * KT;
            for (int idx = t; idx < (NN - 1) * KT; idx += 512)
                rts0[idx >> 2][idx & 3] = rtp[idx];
            if (t < KT) rts0[NN - 1][t] = 0.f;
        }
        const int r = t >> 2, cq = (t & 3) * 16;
        float aggv[16];
#pragma unroll
        for (int c = 0; c < 16; c++) aggv[c] = 0.f;
        for (int k = 0; k < KT; k++) {
            __syncthreads();
            for (int idx = t; idx < 128 * 64; idx += 512) {
                const int rr = idx >> 6, h = idx & 63;
                float val = 0.f;
                if (rr < NN - 1) {
                    const int j = rr + (rr >= i);
                    val = fmaxf(g_U[((b * NN + j) * KT + k) * MHID + h] + vs0[k][h], 0.f);
                }
                h1[rr * 68 + h] = val;
            }
            for (int idx = t; idx < 64 * 64; idx += 512)
                W2s[idx] = W2[k * 64 * 64 + idx];
            __syncthreads();
            float acc[16];
#pragma unroll
            for (int c = 0; c < 16; c++) acc[c] = 0.f;
            for (int kk = 0; kk < 64; kk++) {
                const float a = h1[r * 68 + kk];
#pragma unroll
                for (int c = 0; c < 16; c++)
                    acc[c] = fmaf(a, W2s[kk * 64 + cq + c], acc[c]);
            }
            const float rt = rts0[r][k];
#pragma unroll
            for (int c = 0; c < 16; c++)
                aggv[c] = fmaf(rt, fmaxf(acc[c] + b2s[k][cq + c], 0.f), aggv[c]);
        }
        __syncthreads();
        float* red = (float*)P;
#pragma unroll
        for (int c = 0; c < 16; c++) red[(cq + c) * 132 + r] = aggv[c];
        __syncthreads();
        if (t < 64) {
            float s = 0.f;
            for (int l = 0; l < 128; l++) s += red[t * 132 + l];
            g_AGG[(b * NN + i) * MOUT + t] = s;
        }
        __syncthreads();
    }
#endif
}

// ---------------------------------------------------------------------------
// Node MLP: grid 64 (64 nodes/CTA), 256 threads, weights staged once.
// ---------------------------------------------------------------------------
__global__ __launch_bounds__(256) void node_kernel(
    const float* __restrict__ inp,
    const float* __restrict__ Wo1, const float* __restrict__ bo1,
    const float* __restrict__ Wo2, const float* __restrict__ bo2,
    const float* __restrict__ Wo3, const float* __restrict__ bo3,
    float* __restrict__ out)
{
    extern __shared__ float nsm[];
    float* sW1 = nsm + NOFF_W1;
    float* sW2 = nsm + NOFF_W2;
    float* sW3 = nsm + NOFF_W3;
    float* sB  = nsm + NOFF_B;
    float* aug = nsm + NOFF_AUG;   // [64][81]
    float* h1  = nsm + NOFF_H1;    // [64][65]
    float* h2  = nsm + NOFF_H2;    // [64][65]

    const int t = threadIdx.x;
    const int b = blockIdx.x >> 1, n0 = (blockIdx.x & 1) * 64;

    for (int idx = t; idx < 80 * 64; idx += 256) sW1[idx] = Wo1[idx];
    for (int idx = t; idx < 64 * 64; idx += 256) sW2[idx] = Wo2[idx];
    for (int idx = t; idx < 64 * 16; idx += 256) sW3[idx] = Wo3[idx];
    if (t < 64) sB[t] = bo1[t];
    if (t < 64) sB[64 + t] = bo2[t];
    if (t < 16) sB[128 + t] = bo3[t];

    {
        const int nn = t >> 2, f0 = (t & 3) * 20;
#pragma unroll
        for (int f = f0; f < f0 + 20; f++) {
            aug[nn * 81 + f] = (f < NIN)
                ? inp[(b * NIN + f) * NN + (n0 + nn)]
                : g_AGG[(b * NN + n0 + nn) * MOUT + (f - NIN)];
        }
    }
    __syncthreads();

    const int nn = t & 63, s = t >> 6;
    {
        float acc[16];
#pragma unroll
        for (int x = 0; x < 16; x++) acc[x] = sB[s * 16 + x];
        for (int f = 0; f < NIN + MOUT; f++) {
            const float a = aug[nn * 81 + f];
#pragma unroll
            for (int x = 0; x < 16; x++)
                acc[x] = fmaf(a, sW1[f * 64 + s * 16 + x], acc[x]);
        }
#pragma unroll
        for (int x = 0; x < 16; x++) h1[nn * 65 + s * 16 + x] = fmaxf(acc[x], 0.f);
    }
    __syncthreads();
    {
        float acc[16];
#pragma unroll
        for (int x = 0; x < 16; x++) acc[x] = sB[64 + s * 16 + x];
        for (int f = 0; f < NHID; f++) {
            const float a = h1[nn * 65 + f];
#pragma unroll
            for (int x = 0; x < 16; x++)
                acc[x] = fmaf(a, sW2[f * 64 + s * 16 + x], acc[x]);
        }
#pragma unroll
        for (int x = 0; x < 16; x++) h2[nn * 65 + s * 16 + x] = fmaxf(acc[x], 0.f);
    }
    __syncthreads();
    {
        float acc[4];
#pragma unroll
        for (int x = 0; x < 4; x++) acc[x] = sB[128 + s * 4 + x];
        for (int f = 0; f < NHID; f++) {
            const float a = h2[nn * 65 + f];
#pragma unroll
            for (int x = 0; x < 4; x++)
                acc[x] = fmaf(a, sW3[f * 16 + s * 4 + x], acc[x]);
        }
#pragma unroll
        for (int x = 0; x < 4; x++)
            out[(b * NOUT + s * 4 + x) * NN + (n0 + nn)] = acc[x];
    }
}

// ---------------------------------------------------------------------------
extern "C" void kernel_launch(void* const* d_in, const int* in_sizes, int n_in,
                              void* d_out, int out_size)
{
    const float* inp       = (const float*)d_in[0];
    const float* rel_types = (const float*)d_in[3];
    const float* W1  = (const float*)d_in[4];
    const float* b1  = (const float*)d_in[5];
    const float* W2  = (const float*)d_in[6];
    const float* b2  = (const float*)d_in[7];
    const float* Wo1 = (const float*)d_in[8];
    const float* bo1 = (const float*)d_in[9];
    const float* Wo2 = (const float*)d_in[10];
    const float* bo2 = (const float*)d_in[11];
    const float* Wo3 = (const float*)d_in[12];
    const float* bo3 = (const float*)d_in[13];
    float* out = (float*)d_out;

    (void)cudaFuncSetAttribute(decoder_kernel,
                               cudaFuncAttributeMaxDynamicSharedMemorySize, DEC_DYN);
    (void)cudaFuncSetAttribute(node_kernel,
                               cudaFuncAttributeMaxDynamicSharedMemorySize, NODE_DYN);

    uv_kernel<<<dim3(8, BB), 256>>>(inp, W1, b1, W2);
    decoder_kernel<<<148, 512, DEC_DYN>>>(rel_types, W2, b2);
    node_kernel<<<64, 256, NODE_DYN>>>(inp, Wo1, bo1, Wo2, bo2, Wo3, bo3, out);
}

// round 10
// speedup vs baseline: 1.1929x; 1.1929x over previous
#include <cuda_runtime.h>
#include <cstdint>

#define BB 32
#define NN 128
#define NIN 16
#define MHID 64
#define MOUT 64
#define NHID 64
#define NOUT 16
#define KT 4
#define EDGES (NN * (NN - 1))

// Scratch (no cudaMalloc allowed)
__device__ float g_U[BB * NN * KT * MHID];   // [b][n][k][h] sender proj
__device__ float g_V[BB * NN * KT * MHID];   // [b][n][k][h] receiver proj + b1
__device__ float g_W2T[KT * MOUT * MHID];    // W2 transposed [k][m][kk], tf32-rounded
__device__ float g_AGG[BB * NN * MOUT];      // aggregated messages per node

// ---------------- helpers ----------------
__device__ __forceinline__ uint32_t smem_u32(const void* p) {
    uint32_t a;
    asm("{ .reg .u64 t; cvta.to.shared.u64 t, %1; cvt.u32.u64 %0, t; }" : "=r"(a) : "l"(p));
    return a;
}
__device__ __forceinline__ uint32_t f2tf32(float x) {
    uint32_t r; asm("cvt.rna.tf32.f32 %0, %1;" : "=r"(r) : "f"(x)); return r;
}

#if defined(__CUDA_ARCH_FEAT_SM103_ALL)
__device__ __forceinline__ void mma_tf32_ss(uint32_t d, uint64_t a, uint64_t b,
                                            uint32_t idesc, uint32_t en) {
    asm volatile(
        "{\n\t.reg .pred p;\n\tsetp.ne.u32 p, %4, 0;\n\t"
        "tcgen05.mma.cta_group::1.kind::tf32 [%0], %1, %2, %3, {%5, %5, %5, %5}, p;\n\t}\n"
        :: "r"(d), "l"(a), "l"(b), "r"(idesc), "r"(en), "r"(0u) : "memory");
}
#define MBAR_WAIT_PARITY(addr, ph) do {                                          \
    uint32_t _m = (addr), _p = (ph), _done;                                      \
    asm volatile("{\n\t.reg .pred p;\n\t"                                        \
        "mbarrier.try_wait.parity.acquire.cta.shared::cta.b64 p, [%1], %2;\n\t"  \
        "selp.b32 %0, 1, 0, p;\n\t}" : "=r"(_done) : "r"(_m), "r"(_p) : "memory");\
    if (!_done) {                                                                \
        asm volatile("{\n\t.reg .pred P1;\n\t"                                   \
            "WL_%=:\n\t"                                                         \
            "mbarrier.try_wait.parity.acquire.cta.shared::cta.b64 P1, [%0], %1, 0x989680;\n\t" \
            "@P1 bra.uni WD_%=;\n\tbra.uni WL_%=;\n\tWD_%=:\n\t}"                \
            :: "r"(_m), "r"(_p) : "memory");                                     \
    } } while (0)
#define LDTM_X32(r, addr)                                                        \
    asm volatile("tcgen05.ld.sync.aligned.32x32b.x32.b32 "                       \
        "{%0, %1, %2, %3, %4, %5, %6, %7, %8, %9, %10, %11, %12, %13, %14, %15," \
        " %16, %17, %18, %19, %20, %21, %22, %23, %24, %25, %26, %27, %28, %29, %30, %31}, [%32];" \
        : "=r"((r)[0]),  "=r"((r)[1]),  "=r"((r)[2]),  "=r"((r)[3]),             \
          "=r"((r)[4]),  "=r"((r)[5]),  "=r"((r)[6]),  "=r"((r)[7]),             \
          "=r"((r)[8]),  "=r"((r)[9]),  "=r"((r)[10]), "=r"((r)[11]),            \
          "=r"((r)[12]), "=r"((r)[13]), "=r"((r)[14]), "=r"((r)[15]),            \
          "=r"((r)[16]), "=r"((r)[17]), "=r"((r)[18]), "=r"((r)[19]),            \
          "=r"((r)[20]), "=r"((r)[21]), "=r"((r)[22]), "=r"((r)[23]),            \
          "=r"((r)[24]), "=r"((r)[25]), "=r"((r)[26]), "=r"((r)[27]),            \
          "=r"((r)[28]), "=r"((r)[29]), "=r"((r)[30]), "=r"((r)[31])             \
        : "r"(addr))
#define IDESC_TF32 0x08100910u
#define DESC_BASE ((2ull << 61) | (1ull << 46) | (64ull << 32) | (1ull << 16))
__device__ __forceinline__ uint64_t mk_desc(uint32_t addr) {
    return DESC_BASE | ((uint64_t)(addr >> 4) & 0x3FFF);
}
#endif

// decoder dynamic smem layout (from 1024-aligned base)
#define OFF_B     0          // 4 x 16384 = 65536 (W2T, SW128)
#define OFF_A     65536      // 4 x 32768 = 131072 (h1 tiles, SW128)
#define DEC_DYN   (65536 + 131072 + 1024)

// node-MLP kernel smem (float indices)
#define NOFF_W1   0
#define NOFF_W2   5120
#define NOFF_W3   9216
#define NOFF_B    10240
#define NOFF_AUG  10384      // 64*81
#define NOFF_H1   15568      // 64*65
#define NOFF_H2   19728      // 64*65
#define NODE_DYN  (23888 * 4)

// ---------------------------------------------------------------------------
// uv + fused w2t: grid (8, BB), 256 threads, 16 nodes per CTA.
// ---------------------------------------------------------------------------
__global__ __launch_bounds__(256) void uv_kernel(
    const float* __restrict__ inp, const float* __restrict__ W1,
    const float* __restrict__ b1, const float* __restrict__ W2)
{
    const int g = blockIdx.x, b = blockIdx.y;
    const int n0 = g * 16;
    const int t = threadIdx.x;
    const int k = t >> 6, h = t & 63;

    if (b == 0) {
        for (int idx = g * 2048 + t; idx < (g + 1) * 2048; idx += 256) {
            const int kk2 = idx >> 12, rem = idx & 4095, kki = rem >> 6, m = rem & 63;
            ((uint32_t*)g_W2T)[(kk2 * MOUT + m) * MHID + kki] =
                f2tf32(W2[(kk2 * MHID + kki) * MOUT + m]);
        }
    }

    __shared__ float xs[16][NIN];
    {
        const int nn = t & 15, f = t >> 4;
        xs[nn][f] = inp[(b * NIN + f) * NN + n0 + nn];
    }
    __syncthreads();

    const float* w = W1 + k * (2 * NIN) * MHID;
    const float bv = b1[k * MHID + h];
    float u[16], v[16];
#pragma unroll
    for (int nn = 0; nn < 16; nn++) { u[nn] = 0.f; v[nn] = bv; }
#pragma unroll
    for (int f = 0; f < NIN; f++) {
        const float wu = w[f * MHID + h];
        const float wv = w[(NIN + f) * MHID + h];
#pragma unroll
        for (int nn = 0; nn < 16; nn++) {
            u[nn] = fmaf(xs[nn][f], wu, u[nn]);
            v[nn] = fmaf(xs[nn][f], wv, v[nn]);
        }
    }
#pragma unroll
    for (int nn = 0; nn < 16; nn++) {
        g_U[((b * NN + n0 + nn) * KT + k) * MHID + h] = u[nn];
        g_V[((b * NN + n0 + nn) * KT + k) * MHID + h] = v[nn];
    }
}

// ---------------------------------------------------------------------------
// Persistent warp-specialized decoder: grid 148, 512 threads.
//   warps 0-7  (t 0..255)   : branch-free j-indexed A-build + MMA issue,
//                             half-tile double buffering (k01 / k23)
//   warps 8-15 (t 256..511) : TMEM epilogue + aggregation (rt=0 at j==i)
// ---------------------------------------------------------------------------
__global__ __launch_bounds__(512, 1) void decoder_kernel(
    const float* __restrict__ rel_types, const float* __restrict__ W2,
    const float* __restrict__ b2)
{
    extern __shared__ char dsm[];
    __shared__ float b2s[KT][MOUT];
    __shared__ float part[8][MOUT];
    __shared__ uint32_t tmem_ptr_s;
    __shared__ __align__(8) uint64_t mbar[4];  // [0]=k01 done, [1]=k23 done(all), [2..3]=bank free

    const int t = threadIdx.x;
    const int wid = t >> 5, lane = t & 31;

    const uint32_t dyn = smem_u32(dsm);
    const uint32_t base = (dyn + 1023) & ~1023u;
    char* P = dsm + (base - dyn);

    if (t < 256) b2s[t >> 6][t & 63] = b2[t];

#if defined(__CUDA_ARCH_FEAT_SM103_ALL)
    const uint32_t mb_half  = smem_u32(&mbar[0]);
    const uint32_t mb_mma   = smem_u32(&mbar[1]);
    const uint32_t mb_free0 = smem_u32(&mbar[2]);
    const uint32_t mb_free1 = smem_u32(&mbar[3]);

    // stage 4 B tiles (W2T, SW128) once
    for (int idx = t; idx < KT * 64 * 16; idx += 512) {
        const int k = idx >> 10, n = (idx >> 4) & 63, c = (idx & 15) * 4;
        uint4 w4 = *(const uint4*)((const uint32_t*)g_W2T + (k * MOUT + n) * MHID + c);
        uint32_t byte = ((n >> 3) + (c >> 5) * 8) * 1024 + (n & 7) * 128 + (c & 31) * 4;
        byte ^= (byte >> 3) & 0x70;
        *(uint4*)(P + OFF_B + k * 16384 + byte) = w4;
    }
    if (t == 0) {
        asm volatile("mbarrier.init.shared.b64 [%0], 1;" :: "r"(mb_half) : "memory");
        asm volatile("mbarrier.init.shared.b64 [%0], 1;" :: "r"(mb_mma) : "memory");
        asm volatile("mbarrier.init.shared.b64 [%0], 1;" :: "r"(mb_free0) : "memory");
        asm volatile("mbarrier.init.shared.b64 [%0], 1;" :: "r"(mb_free1) : "memory");
    }
    if (wid == 0) {
        asm volatile("tcgen05.alloc.cta_group::1.sync.aligned.shared::cta.b32 [%0], %1;"
                     :: "r"(smem_u32(&tmem_ptr_s)), "r"(512u) : "memory");
        asm volatile("tcgen05.relinquish_alloc_permit.cta_group::1.sync.aligned;");
    }
    __syncthreads();
    const uint32_t tmem = tmem_ptr_s;

    if (wid < 8) {
        // ========================= BUILDERS =========================
        // thread constants: col group cg, row group rg; rows rg + 16*it keep
        // r&7 constant so the SW128-swizzled STS address is incremental.
        const int cg = t & 15;           // column group (4 floats)
        const int rg = t >> 4;           // 0..15
        const uint32_t stsoff = ((cg >= 8) ? 16384u : 0u) + (uint32_t)(rg >> 3) * 1024u
                              + (uint32_t)(rg & 7) * 128u
                              + ((uint32_t)((cg & 7) ^ (rg & 7)) << 4);
        // j-indexed dense A: row j = relu(u[b,j,k,:] + v_i); diagonal handled
        // by rt=0 in the epilogue.
        const float* ubase = g_U + rg * (KT * MHID) + cg * 4;
        const float* vbase = g_V + cg * 4;

        int phH = 0, phM = 0, phF0 = 0, phF1 = 0, tc = 0;
        for (int tile = blockIdx.x; tile < BB * NN; tile += gridDim.x, tc++) {
            const int b = tile >> 7, i = tile & 127;
            const int q = tc & 1;

            // prefetch v_i for all 4 k (before any wait)
            float4 vv[KT];
#pragma unroll
            for (int k = 0; k < KT; k++)
                vv[k] = *(const float4*)(vbase + (b * NN + i) * (KT * MHID) + k * MHID);

            // ---------- half 0: k = 0,1 ----------
            if (tc > 0) { MBAR_WAIT_PARITY(mb_half, phH); phH ^= 1; }  // A k01 free
#pragma unroll
            for (int k = 0; k < 2; k++) {
                const float* us = ubase + b * (NN * KT * MHID) + k * MHID;
                char* sp = P + OFF_A + k * 32768 + stsoff;
#pragma unroll
                for (int it = 0; it < 8; it++, sp += 2048, us += 16 * KT * MHID) {
                    const float4 u = *(const float4*)us;
                    uint4 w4;
                    w4.x = f2tf32(fmaxf(u.x + vv[k].x, 0.f));
                    w4.y = f2tf32(fmaxf(u.y + vv[k].y, 0.f));
                    w4.z = f2tf32(fmaxf(u.z + vv[k].z, 0.f));
                    w4.w = f2tf32(fmaxf(u.w + vv[k].w, 0.f));
                    *(uint4*)sp = w4;
                }
            }
            asm volatile("bar.sync 1, 256;" ::: "memory");
            if (t == 0) {
                if (tc >= 2) {   // TMEM bank-set q free (epilogue tc-2 done)
                    if (q == 0) { MBAR_WAIT_PARITY(mb_free0, phF0); phF0 ^= 1; }
                    else        { MBAR_WAIT_PARITY(mb_free1, phF1); phF1 ^= 1; }
                }
                asm volatile("fence.proxy.async.shared::cta;" ::: "memory");
#pragma unroll
                for (int k = 0; k < 2; k++) {
                    const uint64_t ad = mk_desc(base + OFF_A + k * 32768);
                    const uint64_t bd = mk_desc(base + OFF_B + k * 16384);
                    const uint32_t dcol = tmem + (q * 4 + k) * 64;
#pragma unroll
                    for (int s = 0; s < 8; s++)
                        mma_tf32_ss(dcol,
                                    ad + ((s >> 2) ? 1024u : 0u) + (s & 3) * 2,
                                    bd + ((s >> 2) ? 512u : 0u) + (s & 3) * 2,
                                    IDESC_TF32, (uint32_t)(s > 0));
                }
                asm volatile(
                    "tcgen05.commit.cta_group::1.mbarrier::arrive::one.shared::cluster.b64 [%0];"
                    :: "r"(mb_half) : "memory");
            }

            // ---------- half 1: k = 2,3 (overlaps GEMM k01) ----------
            if (tc > 0) { MBAR_WAIT_PARITY(mb_mma, phM); phM ^= 1; }  // A k23 free
#pragma unroll
            for (int k = 2; k < 4; k++) {
                const float* us = ubase + b * (NN * KT * MHID) + k * MHID;
                char* sp = P + OFF_A + k * 32768 + stsoff;
#pragma unroll
                for (int it = 0; it < 8; it++, sp += 2048, us += 16 * KT * MHID) {
                    const float4 u = *(const float4*)us;
                    uint4 w4;
                    w4.x = f2tf32(fmaxf(u.x + vv[k].x, 0.f));
                    w4.y = f2tf32(fmaxf(u.y + vv[k].y, 0.f));
                    w4.z = f2tf32(fmaxf(u.z + vv[k].z, 0.f));
                    w4.w = f2tf32(fmaxf(u.w + vv[k].w, 0.f));
                    *(uint4*)sp = w4;
                }
            }
            asm volatile("bar.sync 1, 256;" ::: "memory");
            if (t == 0) {
                asm volatile("fence.proxy.async.shared::cta;" ::: "memory");
#pragma unroll
                for (int k = 2; k < 4; k++) {
                    const uint64_t ad = mk_desc(base + OFF_A + k * 32768);
                    const uint64_t bd = mk_desc(base + OFF_B + k * 16384);
                    const uint32_t dcol = tmem + (q * 4 + k) * 64;
#pragma unroll
                    for (int s = 0; s < 8; s++)
                        mma_tf32_ss(dcol,
                                    ad + ((s >> 2) ? 1024u : 0u) + (s & 3) * 2,
                                    bd + ((s >> 2) ? 512u : 0u) + (s & 3) * 2,
                                    IDESC_TF32, (uint32_t)(s > 0));
                }
                asm volatile(
                    "tcgen05.commit.cta_group::1.mbarrier::arrive::one.shared::cluster.b64 [%0];"
                    :: "r"(mb_mma) : "memory");
            }
        }
    } else {
        // ========================= EPILOGUE =========================
        const int sub = wid & 3;               // TMEM subpartition
        const int kp = (wid >> 2) & 1;         // k pair: {2kp, 2kp+1}
        const int jrow = sub * 32 + lane;      // node j
        const int ewid = wid - 8;

        int phE = 0, tc = 0;
        for (int tile = blockIdx.x; tile < BB * NN; tile += gridDim.x, tc++) {
            const int b = tile >> 7, i = tile & 127;
            const int q = tc & 1;

            // rt weight for node j (0 on the diagonal j==i)
            float2 rt2 = make_float2(0.f, 0.f);
            if (jrow != i) {
                const int e = i * (NN - 1) + jrow - (jrow > i);
                rt2 = *(const float2*)(rel_types +
                        ((size_t)b * EDGES + e) * KT + 2 * kp);
            }

            MBAR_WAIT_PARITY(mb_mma, phE); phE ^= 1;   // all 4 GEMMs(tc) done
            asm volatile("tcgen05.fence::after_thread_sync;" ::: "memory");

#pragma unroll
            for (int chv = 0; chv < 2; chv++) {
                uint32_t d0[32], d1[32];
                LDTM_X32(d0, tmem + (q * 4 + 2 * kp) * 64 + chv * 32);
                LDTM_X32(d1, tmem + (q * 4 + 2 * kp + 1) * 64 + chv * 32);
                asm volatile("tcgen05.wait::ld.sync.aligned;" ::: "memory");
                float a[32];
#pragma unroll
                for (int c = 0; c < 32; c++) {
                    const float v0 = fmaxf(__uint_as_float(d0[c]) + b2s[2 * kp][chv * 32 + c], 0.f);
                    const float v1 = fmaxf(__uint_as_float(d1[c]) + b2s[2 * kp + 1][chv * 32 + c], 0.f);
                    a[c] = rt2.x * v0 + rt2.y * v1;
                }
                // split-butterfly: lane L ends with col L of this 32-col chunk
#pragma unroll
                for (int o = 16; o >= 1; o >>= 1) {
                    const bool up = (lane & o) != 0;
#pragma unroll
                    for (int c = 0; c < 16; c++) {
                        if (c >= o) break;
                        const float send = up ? a[c] : a[c + o];
                        const float keep = up ? a[c + o] : a[c];
                        a[c] = keep + __shfl_xor_sync(0xFFFFFFFFu, send, o);
                    }
                }
                part[ewid][chv * 32 + lane] = a[0];
            }
            asm volatile("tcgen05.fence::before_thread_sync;" ::: "memory");
            asm volatile("bar.sync 2, 256;" ::: "memory");
            if (t == 256) {   // TMEM bank-set q free
                if (q == 0)
                    asm volatile("mbarrier.arrive.shared.b64 _, [%0];" :: "r"(mb_free0) : "memory");
                else
                    asm volatile("mbarrier.arrive.shared.b64 _, [%0];" :: "r"(mb_free1) : "memory");
            }
            {
                const int m = t - 256;
                if (m < 64) {
                    float s = part[0][m];
#pragma unroll
                    for (int w = 1; w < 8; w++) s += part[w][m];
                    g_AGG[(b * NN + i) * MOUT + m] = s;
                }
            }
            asm volatile("bar.sync 2, 256;" ::: "memory");
        }
    }

    __syncthreads();
    if (t == 0) {
        asm volatile("mbarrier.inval.shared.b64 [%0];" :: "r"(mb_half) : "memory");
        asm volatile("mbarrier.inval.shared.b64 [%0];" :: "r"(mb_mma) : "memory");
        asm volatile("mbarrier.inval.shared.b64 [%0];" :: "r"(mb_free0) : "memory");
        asm volatile("mbarrier.inval.shared.b64 [%0];" :: "r"(mb_free1) : "memory");
    }
    if (wid == 0)
        asm volatile("tcgen05.dealloc.cta_group::1.sync.aligned.b32 %0, %1;"
                     :: "r"(tmem), "r"(512u));
#else
    // ============ SIMT fallback (compile-only for plain sm_103) ============
    __shared__ float vs0[KT][MHID];
    __shared__ float rts0[NN][KT];
    float* h1  = (float*)P;
    float* W2s = (float*)(P + 128 * 68 * 4);

    for (int tile = blockIdx.x; tile < BB * NN; tile += gridDim.x) {
        const int b = tile >> 7, i = tile & 127;
        __syncthreads();
        if (t < 256) vs0[t >> 6][t & 63] = g_V[((b * NN + i) * KT) * MHID + t];
        {
            const float* rtp = rel_types + (size_t)(b * EDGES + i * (NN - 1)) * KT;
            for (int idx = t; idx < (NN - 1) * KT; idx += 512)
                rts0[idx >> 2][idx & 3] = rtp[idx];
            if (t < KT) rts0[NN - 1][t] = 0.f;
        }
        const int r = t >> 2, cq = (t & 3) * 16;
        float aggv[16];
#pragma unroll
        for (int c = 0; c < 16; c++) aggv[c] = 0.f;
        for (int k = 0; k < KT; k++) {
            __syncthreads();
            for (int idx = t; idx < 128 * 64; idx += 512) {
                const int rr = idx >> 6, h = idx & 63;
                float val = 0.f;
                if (rr < NN - 1) {
                    const int j = rr + (rr >= i);
                    val = fmaxf(g_U[((b * NN + j) * KT + k) * MHID + h] + vs0[k][h], 0.f);
                }
                h1[rr * 68 + h] = val;
            }
            for (int idx = t; idx < 64 * 64; idx += 512)
                W2s[idx] = W2[k * 64 * 64 + idx];
            __syncthreads();
            float acc[16];
#pragma unroll
            for (int c = 0; c < 16; c++) acc[c] = 0.f;
            for (int kk = 0; kk < 64; kk++) {
                const float a = h1[r * 68 + kk];
#pragma unroll
                for (int c = 0; c < 16; c++)
                    acc[c] = fmaf(a, W2s[kk * 64 + cq + c], acc[c]);
            }
            const float rt = rts0[r][k];
#pragma unroll
            for (int c = 0; c < 16; c++)
                aggv[c] = fmaf(rt, fmaxf(acc[c] + b2s[k][cq + c], 0.f), aggv[c]);
        }
        __syncthreads();
        float* red = (float*)P;
#pragma unroll
        for (int c = 0; c < 16; c++) red[(cq + c) * 132 + r] = aggv[c];
        __syncthreads();
        if (t < 64) {
            float s = 0.f;
            for (int l = 0; l < 128; l++) s += red[t * 132 + l];
            g_AGG[(b * NN + i) * MOUT + t] = s;
        }
        __syncthreads();
    }
#endif
}

// ---------------------------------------------------------------------------
// Node MLP: grid 64 (64 nodes/CTA), 256 threads, weights staged once.
// ---------------------------------------------------------------------------
__global__ __launch_bounds__(256) void node_kernel(
    const float* __restrict__ inp,
    const float* __restrict__ Wo1, const float* __restrict__ bo1,
    const float* __restrict__ Wo2, const float* __restrict__ bo2,
    const float* __restrict__ Wo3, const float* __restrict__ bo3,
    float* __restrict__ out)
{
    extern __shared__ float nsm[];
    float* sW1 = nsm + NOFF_W1;
    float* sW2 = nsm + NOFF_W2;
    float* sW3 = nsm + NOFF_W3;
    float* sB  = nsm + NOFF_B;
    float* aug = nsm + NOFF_AUG;   // [64][81]
    float* h1  = nsm + NOFF_H1;    // [64][65]
    float* h2  = nsm + NOFF_H2;    // [64][65]

    const int t = threadIdx.x;
    const int b = blockIdx.x >> 1, n0 = (blockIdx.x & 1) * 64;

    for (int idx = t; idx < 80 * 64; idx += 256) sW1[idx] = Wo1[idx];
    for (int idx = t; idx < 64 * 64; idx += 256) sW2[idx] = Wo2[idx];
    for (int idx = t; idx < 64 * 16; idx += 256) sW3[idx] = Wo3[idx];
    if (t < 64) sB[t] = bo1[t];
    if (t < 64) sB[64 + t] = bo2[t];
    if (t < 16) sB[128 + t] = bo3[t];

    {
        const int nn = t >> 2, f0 = (t & 3) * 20;
#pragma unroll
        for (int f = f0; f < f0 + 20; f++) {
            aug[nn * 81 + f] = (f < NIN)
                ? inp[(b * NIN + f) * NN + (n0 + nn)]
                : g_AGG[(b * NN + n0 + nn) * MOUT + (f - NIN)];
        }
    }
    __syncthreads();

    const int nn = t & 63, s = t >> 6;
    {
        float acc[16];
#pragma unroll
        for (int x = 0; x < 16; x++) acc[x] = sB[s * 16 + x];
        for (int f = 0; f < NIN + MOUT; f++) {
            const float a = aug[nn * 81 + f];
#pragma unroll
            for (int x = 0; x < 16; x++)
                acc[x] = fmaf(a, sW1[f * 64 + s * 16 + x], acc[x]);
        }
#pragma unroll
        for (int x = 0; x < 16; x++) h1[nn * 65 + s * 16 + x] = fmaxf(acc[x], 0.f);
    }
    __syncthreads();
    {
        float acc[16];
#pragma unroll
        for (int x = 0; x < 16; x++) acc[x] = sB[64 + s * 16 + x];
        for (int f = 0; f < NHID; f++) {
            const float a = h1[nn * 65 + f];
#pragma unroll
            for (int x = 0; x < 16; x++)
                acc[x] = fmaf(a, sW2[f * 64 + s * 16 + x], acc[x]);
        }
#pragma unroll
        for (int x = 0; x < 16; x++) h2[nn * 65 + s * 16 + x] = fmaxf(acc[x], 0.f);
    }
    __syncthreads();
    {
        float acc[4];
#pragma unroll
        for (int x = 0; x < 4; x++) acc[x] = sB[128 + s * 4 + x];
        for (int f = 0; f < NHID; f++) {
            const float a = h2[nn * 65 + f];
#pragma unroll
            for (int x = 0; x < 4; x++)
                acc[x] = fmaf(a, sW3[f * 16 + s * 4 + x], acc[x]);
        }
#pragma unroll
        for (int x = 0; x < 4; x++)
            out[(b * NOUT + s * 4 + x) * NN + (n0 + nn)] = acc[x];
    }
}

// ---------------------------------------------------------------------------
extern "C" void kernel_launch(void* const* d_in, const int* in_sizes, int n_in,
                              void* d_out, int out_size)
{
    const float* inp       = (const float*)d_in[0];
    const float* rel_types = (const float*)d_in[3];
    const float* W1  = (const float*)d_in[4];
    const float* b1  = (const float*)d_in[5];
    const float* W2  = (const float*)d_in[6];
    const float* b2  = (const float*)d_in[7];
    const float* Wo1 = (const float*)d_in[8];
    const float* bo1 = (const float*)d_in[9];
    const float* Wo2 = (const float*)d_in[10];
    const float* bo2 = (const float*)d_in[11];
    const float* Wo3 = (const float*)d_in[12];
    const float* bo3 = (const float*)d_in[13];
    float* out = (float*)d_out;

    (void)cudaFuncSetAttribute(decoder_kernel,
                               cudaFuncAttributeMaxDynamicSharedMemorySize, DEC_DYN);
    (void)cudaFuncSetAttribute(node_kernel,
                               cudaFuncAttributeMaxDynamicSharedMemorySize, NODE_DYN);

    uv_kernel<<<dim3(8, BB), 256>>>(inp, W1, b1, W2);
    decoder_kernel<<<148, 512, DEC_DYN>>>(rel_types, W2, b2);
    node_kernel<<<64, 256, NODE_DYN>>>(inp, Wo1, bo1, Wo2, bo2, Wo3, bo3, out);
}

// round 11
// speedup vs baseline: 1.3439x; 1.1266x over previous
#include <cuda_runtime.h>
#include <cstdint>

#define BB 32
#define NN 128
#define NIN 16
#define MHID 64
#define MOUT 64
#define NHID 64
#define NOUT 16
#define KT 4
#define EDGES (NN * (NN - 1))

// Scratch (no cudaMalloc allowed)
__device__ float g_U[BB * NN * KT * MHID];    // [b][n][k][h] sender proj
__device__ float g_V[BB * NN * KT * MHID];    // [b][n][k][h] receiver proj + b1
__device__ float g_W2T[KT * MOUT * MHID];     // W2 transposed [k][m][kk], tf32
__device__ float g_AGGp[2][BB * NN * MOUT];   // per-kpair partial aggregates

// ---------------- helpers ----------------
__device__ __forceinline__ uint32_t smem_u32(const void* p) {
    uint32_t a;
    asm("{ .reg .u64 t; cvta.to.shared.u64 t, %1; cvt.u32.u64 %0, t; }" : "=r"(a) : "l"(p));
    return a;
}
__device__ __forceinline__ uint32_t f2tf32(float x) {
    uint32_t r; asm("cvt.rna.tf32.f32 %0, %1;" : "=r"(r) : "f"(x)); return r;
}

#if defined(__CUDA_ARCH_FEAT_SM103_ALL)
__device__ __forceinline__ void mma_tf32_ss(uint32_t d, uint64_t a, uint64_t b,
                                            uint32_t idesc, uint32_t en) {
    asm volatile(
        "{\n\t.reg .pred p;\n\tsetp.ne.u32 p, %4, 0;\n\t"
        "tcgen05.mma.cta_group::1.kind::tf32 [%0], %1, %2, %3, {%5, %5, %5, %5}, p;\n\t}\n"
        :: "r"(d), "l"(a), "l"(b), "r"(idesc), "r"(en), "r"(0u) : "memory");
}
#define MBAR_WAIT_PARITY(addr, ph) do {                                          \
    uint32_t _m = (addr), _p = (ph), _done;                                      \
    asm volatile("{\n\t.reg .pred p;\n\t"                                        \
        "mbarrier.try_wait.parity.acquire.cta.shared::cta.b64 p, [%1], %2;\n\t"  \
        "selp.b32 %0, 1, 0, p;\n\t}" : "=r"(_done) : "r"(_m), "r"(_p) : "memory");\
    if (!_done) {                                                                \
        asm volatile("{\n\t.reg .pred P1;\n\t"                                   \
            "WL_%=:\n\t"                                                         \
            "mbarrier.try_wait.parity.acquire.cta.shared::cta.b64 P1, [%0], %1, 0x989680;\n\t" \
            "@P1 bra.uni WD_%=;\n\tbra.uni WL_%=;\n\tWD_%=:\n\t}"                \
            :: "r"(_m), "r"(_p) : "memory");                                     \
    } } while (0)
#define LDTM_X32(r, addr)                                                        \
    asm volatile("tcgen05.ld.sync.aligned.32x32b.x32.b32 "                       \
        "{%0, %1, %2, %3, %4, %5, %6, %7, %8, %9, %10, %11, %12, %13, %14, %15," \
        " %16, %17, %18, %19, %20, %21, %22, %23, %24, %25, %26, %27, %28, %29, %30, %31}, [%32];" \
        : "=r"((r)[0]),  "=r"((r)[1]),  "=r"((r)[2]),  "=r"((r)[3]),             \
          "=r"((r)[4]),  "=r"((r)[5]),  "=r"((r)[6]),  "=r"((r)[7]),             \
          "=r"((r)[8]),  "=r"((r)[9]),  "=r"((r)[10]), "=r"((r)[11]),            \
          "=r"((r)[12]), "=r"((r)[13]), "=r"((r)[14]), "=r"((r)[15]),            \
          "=r"((r)[16]), "=r"((r)[17]), "=r"((r)[18]), "=r"((r)[19]),            \
          "=r"((r)[20]), "=r"((r)[21]), "=r"((r)[22]), "=r"((r)[23]),            \
          "=r"((r)[24]), "=r"((r)[25]), "=r"((r)[26]), "=r"((r)[27]),            \
          "=r"((r)[28]), "=r"((r)[29]), "=r"((r)[30]), "=r"((r)[31])             \
        : "r"(addr))
#define IDESC_TF32 0x08100910u
#define DESC_BASE ((2ull << 61) | (1ull << 46) | (64ull << 32) | (1ull << 16))
__device__ __forceinline__ uint64_t mk_desc(uint32_t addr) {
    return DESC_BASE | ((uint64_t)(addr >> 4) & 0x3FFF);
}
#endif

// decoder dynamic smem layout (from 1024-aligned base); per-CTA (k-split)
#define OFF_B     0          // 2 x 16384 = 32768 (W2T, SW128)
#define OFF_A     32768      // 2 x 32768 = 65536 (h1 tiles, SW128)
#define DEC_DYN   (32768 + 65536 + 1024)

// node-MLP kernel smem (float indices)
#define NOFF_W1   0
#define NOFF_W2   5120
#define NOFF_W3   9216
#define NOFF_B    10240
#define NOFF_AUG  10384      // 64*81
#define NOFF_H1   15568      // 64*65
#define NOFF_H2   19728      // 64*65
#define NODE_DYN  (23888 * 4)

// ---------------------------------------------------------------------------
// uv + fused w2t: grid (8, BB), 256 threads, 16 nodes per CTA.
// ---------------------------------------------------------------------------
__global__ __launch_bounds__(256) void uv_kernel(
    const float* __restrict__ inp, const float* __restrict__ W1,
    const float* __restrict__ b1, const float* __restrict__ W2)
{
    const int g = blockIdx.x, b = blockIdx.y;
    const int n0 = g * 16;
    const int t = threadIdx.x;
    const int k = t >> 6, h = t & 63;

    if (b == 0) {
        for (int idx = g * 2048 + t; idx < (g + 1) * 2048; idx += 256) {
            const int kk2 = idx >> 12, rem = idx & 4095, kki = rem >> 6, m = rem & 63;
            ((uint32_t*)g_W2T)[(kk2 * MOUT + m) * MHID + kki] =
                f2tf32(W2[(kk2 * MHID + kki) * MOUT + m]);
        }
    }

    __shared__ float xs[16][NIN];
    {
        const int nn = t & 15, f = t >> 4;
        xs[nn][f] = inp[(b * NIN + f) * NN + n0 + nn];
    }
    __syncthreads();

    const float* w = W1 + k * (2 * NIN) * MHID;
    const float bv = b1[k * MHID + h];
    float u[16], v[16];
#pragma unroll
    for (int nn = 0; nn < 16; nn++) { u[nn] = 0.f; v[nn] = bv; }
#pragma unroll
    for (int f = 0; f < NIN; f++) {
        const float wu = w[f * MHID + h];
        const float wv = w[(NIN + f) * MHID + h];
#pragma unroll
        for (int nn = 0; nn < 16; nn++) {
            u[nn] = fmaf(xs[nn][f], wu, u[nn]);
            v[nn] = fmaf(xs[nn][f], wv, v[nn]);
        }
    }
#pragma unroll
    for (int nn = 0; nn < 16; nn++) {
        g_U[((b * NN + n0 + nn) * KT + k) * MHID + h] = u[nn];
        g_V[((b * NN + n0 + nn) * KT + k) * MHID + h] = v[nn];
    }
}

// ---------------------------------------------------------------------------
// Persistent k-split decoder: grid 296, 256 threads, 2 CTAs per SM.
// CTA parity kp handles edge-types {2kp, 2kp+1} for every tile.
//   warps 0-3 (t 0..127)   : branch-free A-build + MMA issue (per-k gating)
//   warps 4-7 (t 128..255) : TMEM epilogue + partial aggregation
// ---------------------------------------------------------------------------
__global__ __launch_bounds__(256, 2) void decoder_kernel(
    const float* __restrict__ rel_types, const float* __restrict__ W2,
    const float* __restrict__ b2)
{
    extern __shared__ char dsm[];
    __shared__ float b2s[2][MOUT];
    __shared__ float part[4][MOUT];
    __shared__ uint32_t tmem_ptr_s;
    __shared__ __align__(8) uint64_t mbar[4];  // [0]=ka done, [1]=kb done, [2..3]=bank free

    const int t = threadIdx.x;
    const int wid = t >> 5, lane = t & 31;
    const int kp = blockIdx.x & 1;             // k pair owned by this CTA
    const int tile0 = blockIdx.x >> 1;         // 0..147

    const uint32_t dyn = smem_u32(dsm);
    const uint32_t base = (dyn + 1023) & ~1023u;
    char* P = dsm + (base - dyn);

    if (t < 128) b2s[t >> 6][t & 63] = b2[kp * 128 + t];

#if defined(__CUDA_ARCH_FEAT_SM103_ALL)
    const uint32_t mb_a     = smem_u32(&mbar[0]);
    const uint32_t mb_mma   = smem_u32(&mbar[1]);
    const uint32_t mb_free0 = smem_u32(&mbar[2]);
    const uint32_t mb_free1 = smem_u32(&mbar[3]);

    // stage this CTA's 2 B tiles (W2T, SW128) once
    for (int idx = t; idx < 2 * 64 * 16; idx += 256) {
        const int kk = idx >> 10, n = (idx >> 4) & 63, c = (idx & 15) * 4;
        uint4 w4 = *(const uint4*)((const uint32_t*)g_W2T +
                                   ((2 * kp + kk) * MOUT + n) * MHID + c);
        uint32_t byte = ((n >> 3) + (c >> 5) * 8) * 1024 + (n & 7) * 128 + (c & 31) * 4;
        byte ^= (byte >> 3) & 0x70;
        *(uint4*)(P + OFF_B + kk * 16384 + byte) = w4;
    }
    if (t == 0) {
        asm volatile("mbarrier.init.shared.b64 [%0], 1;" :: "r"(mb_a) : "memory");
        asm volatile("mbarrier.init.shared.b64 [%0], 1;" :: "r"(mb_mma) : "memory");
        asm volatile("mbarrier.init.shared.b64 [%0], 1;" :: "r"(mb_free0) : "memory");
        asm volatile("mbarrier.init.shared.b64 [%0], 1;" :: "r"(mb_free1) : "memory");
    }
    if (wid == 0) {
        asm volatile("tcgen05.alloc.cta_group::1.sync.aligned.shared::cta.b32 [%0], %1;"
                     :: "r"(smem_u32(&tmem_ptr_s)), "r"(256u) : "memory");
        asm volatile("tcgen05.relinquish_alloc_permit.cta_group::1.sync.aligned;");
    }
    __syncthreads();
    const uint32_t tmem = tmem_ptr_s;

    if (wid < 4) {
        // ========================= BUILDERS =========================
        // thread constants: col group cg, row base rg; rows rg + 8*it keep
        // r&7 constant so the SW128-swizzled STS address steps by +1024 B.
        const int cg = t & 15;               // column group (4 floats)
        const int rg = (t >> 4) & 7;         // 0..7
        const uint32_t stsoff = ((cg >= 8) ? 16384u : 0u) + (uint32_t)rg * 128u
                              + ((uint32_t)((cg & 7) ^ rg) << 4);
        const float* ubase = g_U + rg * (KT * MHID) + cg * 4;
        const float* vbase = g_V + cg * 4;

        int phA = 0, phM = 0, phF0 = 0, phF1 = 0, tc = 0;
        for (int tile = tile0; tile < BB * NN; tile += 148, tc++) {
            const int b = tile >> 7, i = tile & 127;
            const int q = tc & 1;

            // prefetch v_i for both k (before any wait)
            float4 vv[2];
#pragma unroll
            for (int kk = 0; kk < 2; kk++)
                vv[kk] = *(const float4*)(vbase + (b * NN + i) * (KT * MHID)
                                          + (2 * kp + kk) * MHID);

            // ---------- k_a ----------
            if (tc > 0) { MBAR_WAIT_PARITY(mb_a, phA); phA ^= 1; }  // A_ka free
            {
                const float* us = ubase + b * (NN * KT * MHID) + (2 * kp) * MHID;
                char* sp = P + OFF_A + stsoff;
#pragma unroll
                for (int it = 0; it < 16; it++, sp += 1024, us += 8 * KT * MHID) {
                    const float4 u = *(const float4*)us;
                    uint4 w4;
                    w4.x = f2tf32(fmaxf(u.x + vv[0].x, 0.f));
                    w4.y = f2tf32(fmaxf(u.y + vv[0].y, 0.f));
                    w4.z = f2tf32(fmaxf(u.z + vv[0].z, 0.f));
                    w4.w = f2tf32(fmaxf(u.w + vv[0].w, 0.f));
                    *(uint4*)sp = w4;
                }
            }
            asm volatile("bar.sync 1, 128;" ::: "memory");
            if (t == 0) {
                if (tc >= 2) {   // TMEM bank-set q free (epilogue tc-2 done)
                    if (q == 0) { MBAR_WAIT_PARITY(mb_free0, phF0); phF0 ^= 1; }
                    else        { MBAR_WAIT_PARITY(mb_free1, phF1); phF1 ^= 1; }
                }
                asm volatile("fence.proxy.async.shared::cta;" ::: "memory");
                const uint64_t ad = mk_desc(base + OFF_A);
                const uint64_t bd = mk_desc(base + OFF_B);
                const uint32_t dcol = tmem + (q * 2) * 64;
#pragma unroll
                for (int s = 0; s < 8; s++)
                    mma_tf32_ss(dcol,
                                ad + ((s >> 2) ? 1024u : 0u) + (s & 3) * 2,
                                bd + ((s >> 2) ? 512u : 0u) + (s & 3) * 2,
                                IDESC_TF32, (uint32_t)(s > 0));
                asm volatile(
                    "tcgen05.commit.cta_group::1.mbarrier::arrive::one.shared::cluster.b64 [%0];"
                    :: "r"(mb_a) : "memory");
            }

            // ---------- k_b (build overlaps GEMM k_a) ----------
            if (tc > 0) { MBAR_WAIT_PARITY(mb_mma, phM); phM ^= 1; }  // A_kb free
            {
                const float* us = ubase + b * (NN * KT * MHID) + (2 * kp + 1) * MHID;
                char* sp = P + OFF_A + 32768 + stsoff;
#pragma unroll
                for (int it = 0; it < 16; it++, sp += 1024, us += 8 * KT * MHID) {
                    const float4 u = *(const float4*)us;
                    uint4 w4;
                    w4.x = f2tf32(fmaxf(u.x + vv[1].x, 0.f));
                    w4.y = f2tf32(fmaxf(u.y + vv[1].y, 0.f));
                    w4.z = f2tf32(fmaxf(u.z + vv[1].z, 0.f));
                    w4.w = f2tf32(fmaxf(u.w + vv[1].w, 0.f));
                    *(uint4*)sp = w4;
                }
            }
            asm volatile("bar.sync 1, 128;" ::: "memory");
            if (t == 0) {
                asm volatile("fence.proxy.async.shared::cta;" ::: "memory");
                const uint64_t ad = mk_desc(base + OFF_A + 32768);
                const uint64_t bd = mk_desc(base + OFF_B + 16384);
                const uint32_t dcol = tmem + (q * 2 + 1) * 64;
#pragma unroll
                for (int s = 0; s < 8; s++)
                    mma_tf32_ss(dcol,
                                ad + ((s >> 2) ? 1024u : 0u) + (s & 3) * 2,
                                bd + ((s >> 2) ? 512u : 0u) + (s & 3) * 2,
                                IDESC_TF32, (uint32_t)(s > 0));
                asm volatile(
                    "tcgen05.commit.cta_group::1.mbarrier::arrive::one.shared::cluster.b64 [%0];"
                    :: "r"(mb_mma) : "memory");
            }
        }
    } else {
        // ========================= EPILOGUE =========================
        const int sub = wid - 4;               // TMEM subpartition
        const int jrow = sub * 32 + lane;      // node j
        int phE = 0, tc = 0;
        for (int tile = tile0; tile < BB * NN; tile += 148, tc++) {
            const int b = tile >> 7, i = tile & 127;
            const int q = tc & 1;

            // rt weight for node j (0 on the diagonal j==i)
            float2 rt2 = make_float2(0.f, 0.f);
            if (jrow != i) {
                const int e = i * (NN - 1) + jrow - (jrow > i);
                rt2 = *(const float2*)(rel_types +
                        ((size_t)b * EDGES + e) * KT + 2 * kp);
            }

            MBAR_WAIT_PARITY(mb_mma, phE); phE ^= 1;   // both GEMMs(tc) done
            asm volatile("tcgen05.fence::after_thread_sync;" ::: "memory");

#pragma unroll
            for (int chv = 0; chv < 2; chv++) {
                uint32_t d0[32], d1[32];
                LDTM_X32(d0, tmem + (q * 2 + 0) * 64 + chv * 32);
                LDTM_X32(d1, tmem + (q * 2 + 1) * 64 + chv * 32);
                asm volatile("tcgen05.wait::ld.sync.aligned;" ::: "memory");
                float a[32];
#pragma unroll
                for (int c = 0; c < 32; c++) {
                    const float v0 = fmaxf(__uint_as_float(d0[c]) + b2s[0][chv * 32 + c], 0.f);
                    const float v1 = fmaxf(__uint_as_float(d1[c]) + b2s[1][chv * 32 + c], 0.f);
                    a[c] = rt2.x * v0 + rt2.y * v1;
                }
                // split-butterfly: lane L ends with col L of this 32-col chunk
#pragma unroll
                for (int o = 16; o >= 1; o >>= 1) {
                    const bool up = (lane & o) != 0;
#pragma unroll
                    for (int c = 0; c < 16; c++) {
                        if (c >= o) break;
                        const float send = up ? a[c] : a[c + o];
                        const float keep = up ? a[c + o] : a[c];
                        a[c] = keep + __shfl_xor_sync(0xFFFFFFFFu, send, o);
                    }
                }
                part[sub][chv * 32 + lane] = a[0];
            }
            asm volatile("tcgen05.fence::before_thread_sync;" ::: "memory");
            asm volatile("bar.sync 2, 128;" ::: "memory");
            if (t == 128) {   // TMEM bank-set q free
                if (q == 0)
                    asm volatile("mbarrier.arrive.shared.b64 _, [%0];" :: "r"(mb_free0) : "memory");
                else
                    asm volatile("mbarrier.arrive.shared.b64 _, [%0];" :: "r"(mb_free1) : "memory");
            }
            {
                const int m = t - 128;
                if (m < 64)
                    g_AGGp[kp][(b * NN + i) * MOUT + m] =
                        part[0][m] + part[1][m] + part[2][m] + part[3][m];
            }
            asm volatile("bar.sync 2, 128;" ::: "memory");
        }
    }

    __syncthreads();
    if (t == 0) {
        asm volatile("mbarrier.inval.shared.b64 [%0];" :: "r"(mb_a) : "memory");
        asm volatile("mbarrier.inval.shared.b64 [%0];" :: "r"(mb_mma) : "memory");
        asm volatile("mbarrier.inval.shared.b64 [%0];" :: "r"(mb_free0) : "memory");
        asm volatile("mbarrier.inval.shared.b64 [%0];" :: "r"(mb_free1) : "memory");
    }
    if (wid == 0)
        asm volatile("tcgen05.dealloc.cta_group::1.sync.aligned.b32 %0, %1;"
                     :: "r"(tmem), "r"(256u));
#else
    // ============ SIMT fallback (compile-only for plain sm_103) ============
    __shared__ float vs0[2][MHID];
    __shared__ float rts0[NN][2];
    float* h1  = (float*)P;                  // [128][68]
    float* W2s = (float*)(P + 128 * 68 * 4); // [64][64]

    for (int tile = tile0; tile < BB * NN; tile += 148) {
        const int b = tile >> 7, i = tile & 127;
        __syncthreads();
        if (t < 128) vs0[t >> 6][t & 63] =
            g_V[((b * NN + i) * KT + 2 * kp) * MHID + t];
        for (int idx = t; idx < NN * 2; idx += 256) {
            const int j = idx >> 1, kk = idx & 1;
            float rt = 0.f;
            if (j != i) {
                const int e = i * (NN - 1) + j - (j > i);
                rt = rel_types[((size_t)b * EDGES + e) * KT + 2 * kp + kk];
            }
            rts0[j][kk] = rt;
        }
        const int r = t >> 1, cq = (t & 1) * 32;
        float aggv[32];
#pragma unroll
        for (int c = 0; c < 32; c++) aggv[c] = 0.f;
        for (int kk = 0; kk < 2; kk++) {
            __syncthreads();
            for (int idx = t; idx < 128 * 64; idx += 256) {
                const int rr = idx >> 6, h = idx & 63;
                h1[rr * 68 + h] = fmaxf(
                    g_U[((b * NN + rr) * KT + 2 * kp + kk) * MHID + h] + vs0[kk][h], 0.f);
            }
            for (int idx = t; idx < 64 * 64; idx += 256)
                W2s[idx] = W2[(2 * kp + kk) * 64 * 64 + idx];
            __syncthreads();
            float acc[32];
#pragma unroll
            for (int c = 0; c < 32; c++) acc[c] = 0.f;
            for (int kkk = 0; kkk < 64; kkk++) {
                const float a = h1[r * 68 + kkk];
#pragma unroll
                for (int c = 0; c < 32; c++)
                    acc[c] = fmaf(a, W2s[kkk * 64 + cq + c], acc[c]);
            }
            const float rt = rts0[r][kk];
#pragma unroll
            for (int c = 0; c < 32; c++)
                aggv[c] = fmaf(rt, fmaxf(acc[c] + b2s[kk][cq + c], 0.f), aggv[c]);
        }
        __syncthreads();
        float* red = (float*)P;  // [64 m][stride 132]
#pragma unroll
        for (int c = 0; c < 32; c++) red[(cq + c) * 132 + r] = aggv[c];
        __syncthreads();
        if (t < 64) {
            float s = 0.f;
            for (int l = 0; l < 128; l++) s += red[t * 132 + l];
            g_AGGp[kp][(b * NN + i) * MOUT + t] = s;
        }
        __syncthreads();
    }
#endif
}

// ---------------------------------------------------------------------------
// Node MLP: grid 64 (64 nodes/CTA), 256 threads, weights staged once.
// ---------------------------------------------------------------------------
__global__ __launch_bounds__(256) void node_kernel(
    const float* __restrict__ inp,
    const float* __restrict__ Wo1, const float* __restrict__ bo1,
    const float* __restrict__ Wo2, const float* __restrict__ bo2,
    const float* __restrict__ Wo3, const float* __restrict__ bo3,
    float* __restrict__ out)
{
    extern __shared__ float nsm[];
    float* sW1 = nsm + NOFF_W1;
    float* sW2 = nsm + NOFF_W2;
    float* sW3 = nsm + NOFF_W3;
    float* sB  = nsm + NOFF_B;
    float* aug = nsm + NOFF_AUG;   // [64][81]
    float* h1  = nsm + NOFF_H1;    // [64][65]
    float* h2  = nsm + NOFF_H2;    // [64][65]

    const int t = threadIdx.x;
    const int b = blockIdx.x >> 1, n0 = (blockIdx.x & 1) * 64;

    for (int idx = t; idx < 80 * 64; idx += 256) sW1[idx] = Wo1[idx];
    for (int idx = t; idx < 64 * 64; idx += 256) sW2[idx] = Wo2[idx];
    for (int idx = t; idx < 64 * 16; idx += 256) sW3[idx] = Wo3[idx];
    if (t < 64) sB[t] = bo1[t];
    if (t < 64) sB[64 + t] = bo2[t];
    if (t < 16) sB[128 + t] = bo3[t];

    {
        const int nn = t >> 2, f0 = (t & 3) * 20;
#pragma unroll
        for (int f = f0; f < f0 + 20; f++) {
            float val;
            if (f < NIN) {
                val = inp[(b * NIN + f) * NN + (n0 + nn)];
            } else {
                const int idx = (b * NN + n0 + nn) * MOUT + (f - NIN);
                val = g_AGGp[0][idx] + g_AGGp[1][idx];
            }
            aug[nn * 81 + f] = val;
        }
    }
    __syncthreads();

    const int nn = t & 63, s = t >> 6;
    {
        float acc[16];
#pragma unroll
        for (int x = 0; x < 16; x++) acc[x] = sB[s * 16 + x];
        for (int f = 0; f < NIN + MOUT; f++) {
            const float a = aug[nn * 81 + f];
#pragma unroll
            for (int x = 0; x < 16; x++)
                acc[x] = fmaf(a, sW1[f * 64 + s * 16 + x], acc[x]);
        }
#pragma unroll
        for (int x = 0; x < 16; x++) h1[nn * 65 + s * 16 + x] = fmaxf(acc[x], 0.f);
    }
    __syncthreads();
    {
        float acc[16];
#pragma unroll
        for (int x = 0; x < 16; x++) acc[x] = sB[64 + s * 16 + x];
        for (int f = 0; f < NHID; f++) {
            const float a = h1[nn * 65 + f];
#pragma unroll
            for (int x = 0; x < 16; x++)
                acc[x] = fmaf(a, sW2[f * 64 + s * 16 + x], acc[x]);
        }
#pragma unroll
        for (int x = 0; x < 16; x++) h2[nn * 65 + s * 16 + x] = fmaxf(acc[x], 0.f);
    }
    __syncthreads();
    {
        float acc[4];
#pragma unroll
        for (int x = 0; x < 4; x++) acc[x] = sB[128 + s * 4 + x];
        for (int f = 0; f < NHID; f++) {
            const float a = h2[nn * 65 + f];
#pragma unroll
            for (int x = 0; x < 4; x++)
                acc[x] = fmaf(a, sW3[f * 16 + s * 4 + x], acc[x]);
        }
#pragma unroll
        for (int x = 0; x < 4; x++)
            out[(b * NOUT + s * 4 + x) * NN + (n0 + nn)] = acc[x];
    }
}

// ---------------------------------------------------------------------------
extern "C" void kernel_launch(void* const* d_in, const int* in_sizes, int n_in,
                              void* d_out, int out_size)
{
    const float* inp       = (const float*)d_in[0];
    const float* rel_types = (const float*)d_in[3];
    const float* W1  = (const float*)d_in[4];
    const float* b1  = (const float*)d_in[5];
    const float* W2  = (const float*)d_in[6];
    const float* b2  = (const float*)d_in[7];
    const float* Wo1 = (const float*)d_in[8];
    const float* bo1 = (const float*)d_in[9];
    const float* Wo2 = (const float*)d_in[10];
    const float* bo2 = (const float*)d_in[11];
    const float* Wo3 = (const float*)d_in[12];
    const float* bo3 = (const float*)d_in[13];
    float* out = (float*)d_out;

    (void)cudaFuncSetAttribute(decoder_kernel,
                               cudaFuncAttributeMaxDynamicSharedMemorySize, DEC_DYN);
    (void)cudaFuncSetAttribute(node_kernel,
                               cudaFuncAttributeMaxDynamicSharedMemorySize, NODE_DYN);

    uv_kernel<<<dim3(8, BB), 256>>>(inp, W1, b1, W2);
    decoder_kernel<<<296, 256, DEC_DYN>>>(rel_types, W2, b2);
    node_kernel<<<64, 256, NODE_DYN>>>(inp, Wo1, bo1, Wo2, bo2, Wo3, bo3, out);
}

// round 13
// speedup vs baseline: 1.3622x; 1.0136x over previous
#include <cuda_runtime.h>
#include <cstdint>

#define BB 32
#define NN 128
#define NIN 16
#define MHID 64
#define MOUT 64
#define NHID 64
#define NOUT 16
#define KT 4
#define EDGES (NN * (NN - 1))

// Scratch (no cudaMalloc allowed)
__device__ float g_U[BB * NN * KT * MHID];    // [b][n][k][h] sender proj
__device__ float g_V[BB * NN * KT * MHID];    // [b][n][k][h] receiver proj + b1
__device__ float g_W2T[KT * MOUT * MHID];     // W2 transposed [k][m][kk], tf32
__device__ float g_AGGp[KT][BB * NN * MOUT];  // per-k partial aggregates

// ---------------- helpers ----------------
__device__ __forceinline__ uint32_t smem_u32(const void* p) {
    uint32_t a;
    asm("{ .reg .u64 t; cvta.to.shared.u64 t, %1; cvt.u32.u64 %0, t; }" : "=r"(a) : "l"(p));
    return a;
}
__device__ __forceinline__ uint32_t f2tf32(float x) {
    uint32_t r; asm("cvt.rna.tf32.f32 %0, %1;" : "=r"(r) : "f"(x)); return r;
}

#if defined(__CUDA_ARCH_FEAT_SM103_ALL)
__device__ __forceinline__ void mma_tf32_ss(uint32_t d, uint64_t a, uint64_t b,
                                            uint32_t idesc, uint32_t en) {
    asm volatile(
        "{\n\t.reg .pred p;\n\tsetp.ne.u32 p, %4, 0;\n\t"
        "tcgen05.mma.cta_group::1.kind::tf32 [%0], %1, %2, %3, {%5, %5, %5, %5}, p;\n\t}\n"
        :: "r"(d), "l"(a), "l"(b), "r"(idesc), "r"(en), "r"(0u) : "memory");
}
#define MBAR_WAIT_PARITY(addr, ph) do {                                          \
    uint32_t _m = (addr), _p = (ph), _done;                                      \
    asm volatile("{\n\t.reg .pred p;\n\t"                                        \
        "mbarrier.try_wait.parity.acquire.cta.shared::cta.b64 p, [%1], %2;\n\t"  \
        "selp.b32 %0, 1, 0, p;\n\t}" : "=r"(_done) : "r"(_m), "r"(_p) : "memory");\
    if (!_done) {                                                                \
        asm volatile("{\n\t.reg .pred P1;\n\t"                                   \
            "WL_%=:\n\t"                                                         \
            "mbarrier.try_wait.parity.acquire.cta.shared::cta.b64 P1, [%0], %1, 0x989680;\n\t" \
            "@P1 bra.uni WD_%=;\n\tbra.uni WL_%=;\n\tWD_%=:\n\t}"                \
            :: "r"(_m), "r"(_p) : "memory");                                     \
    } } while (0)
#define LDTM_X32(r, addr)                                                        \
    asm volatile("tcgen05.ld.sync.aligned.32x32b.x32.b32 "                       \
        "{%0, %1, %2, %3, %4, %5, %6, %7, %8, %9, %10, %11, %12, %13, %14, %15," \
        " %16, %17, %18, %19, %20, %21, %22, %23, %24, %25, %26, %27, %28, %29, %30, %31}, [%32];" \
        : "=r"((r)[0]),  "=r"((r)[1]),  "=r"((r)[2]),  "=r"((r)[3]),             \
          "=r"((r)[4]),  "=r"((r)[5]),  "=r"((r)[6]),  "=r"((r)[7]),             \
          "=r"((r)[8]),  "=r"((r)[9]),  "=r"((r)[10]), "=r"((r)[11]),            \
          "=r"((r)[12]), "=r"((r)[13]), "=r"((r)[14]), "=r"((r)[15]),            \
          "=r"((r)[16]), "=r"((r)[17]), "=r"((r)[18]), "=r"((r)[19]),            \
          "=r"((r)[20]), "=r"((r)[21]), "=r"((r)[22]), "=r"((r)[23]),            \
          "=r"((r)[24]), "=r"((r)[25]), "=r"((r)[26]), "=r"((r)[27]),            \
          "=r"((r)[28]), "=r"((r)[29]), "=r"((r)[30]), "=r"((r)[31])             \
        : "r"(addr))
#define IDESC_TF32 0x08100910u
#define DESC_BASE ((2ull << 61) | (1ull << 46) | (64ull << 32) | (1ull << 16))
__device__ __forceinline__ uint64_t mk_desc(uint32_t addr) {
    return DESC_BASE | ((uint64_t)(addr >> 4) & 0x3FFF);
}
#endif

// decoder dynamic smem layout (from 1024-aligned base); per-CTA (1 edge-type)
#define OFF_B     0          // 16384 (W2T, SW128)
#define OFF_A     16384      // 32768 (h1 tile, SW128)
#define DEC_DYN   (16384 + 32768 + 1024)

// node-MLP kernel smem (float indices)
#define NOFF_W1   0
#define NOFF_W2   5120
#define NOFF_W3   9216
#define NOFF_B    10240
#define NOFF_AUG  10384      // 64*81
#define NOFF_H1   15568      // 64*65
#define NOFF_H2   19728      // 64*65
#define NODE_DYN  (23888 * 4)

// ---------------------------------------------------------------------------
// uv + fused w2t: grid (8, BB), 256 threads, 16 nodes per CTA.
// ---------------------------------------------------------------------------
__global__ __launch_bounds__(256) void uv_kernel(
    const float* __restrict__ inp, const float* __restrict__ W1,
    const float* __restrict__ b1, const float* __restrict__ W2)
{
    const int g = blockIdx.x, b = blockIdx.y;
    const int n0 = g * 16;
    const int t = threadIdx.x;
    const int k = t >> 6, h = t & 63;

    if (b == 0) {
        for (int idx = g * 2048 + t; idx < (g + 1) * 2048; idx += 256) {
            const int kk2 = idx >> 12, rem = idx & 4095, kki = rem >> 6, m = rem & 63;
            ((uint32_t*)g_W2T)[(kk2 * MOUT + m) * MHID + kki] =
                f2tf32(W2[(kk2 * MHID + kki) * MOUT + m]);
        }
    }

    __shared__ float xs[16][NIN];
    {
        const int nn = t & 15, f = t >> 4;
        xs[nn][f] = inp[(b * NIN + f) * NN + n0 + nn];
    }
    __syncthreads();

    const float* w = W1 + k * (2 * NIN) * MHID;
    const float bv = b1[k * MHID + h];
    float u[16], v[16];
#pragma unroll
    for (int nn = 0; nn < 16; nn++) { u[nn] = 0.f; v[nn] = bv; }
#pragma unroll
    for (int f = 0; f < NIN; f++) {
        const float wu = w[f * MHID + h];
        const float wv = w[(NIN + f) * MHID + h];
#pragma unroll
        for (int nn = 0; nn < 16; nn++) {
            u[nn] = fmaf(xs[nn][f], wu, u[nn]);
            v[nn] = fmaf(xs[nn][f], wv, v[nn]);
        }
    }
#pragma unroll
    for (int nn = 0; nn < 16; nn++) {
        g_U[((b * NN + n0 + nn) * KT + k) * MHID + h] = u[nn];
        g_V[((b * NN + n0 + nn) * KT + k) * MHID + h] = v[nn];
    }
}

// ---------------------------------------------------------------------------
// Persistent k-split decoder: grid 592, 256 threads, 4 CTAs per SM.
// CTA kp = blockIdx.x & 3 owns edge-type kp for every tile.
//   warps 0-3 (t 0..127)   : branch-free A-build + MMA issue
//   warps 4-7 (t 128..255) : TMEM epilogue + partial aggregation
// TMEM: 64 cols per CTA, SINGLE buffer (4 x 64 = 256 of 512 — slack for the
// allocator). GEMM(tc) gated on epilogue(tc-1) read-done via mb_free.
// Epilogue uses one in-place register array (no spills at 64-reg cap).
// ---------------------------------------------------------------------------
__global__ __launch_bounds__(256, 4) void decoder_kernel(
    const float* __restrict__ rel_types, const float* __restrict__ W2,
    const float* __restrict__ b2)
{
    extern __shared__ char dsm[];
    __shared__ float b2s[MOUT];
    __shared__ float part[4][MOUT];
    __shared__ uint32_t tmem_ptr_s;
    __shared__ __align__(8) uint64_t mbar[2];  // [0]=mma done, [1]=bank free

    const int t = threadIdx.x;
    const int wid = t >> 5, lane = t & 31;
    const int kp = blockIdx.x & 3;             // edge-type owned by this CTA
    const int tile0 = blockIdx.x >> 2;         // 0..147

    const uint32_t dyn = smem_u32(dsm);
    const uint32_t base = (dyn + 1023) & ~1023u;
    char* P = dsm + (base - dyn);

    if (t < 64) b2s[t] = b2[kp * 64 + t];

#if defined(__CUDA_ARCH_FEAT_SM103_ALL)
    const uint32_t mb_mma  = smem_u32(&mbar[0]);
    const uint32_t mb_free = smem_u32(&mbar[1]);

    // stage this CTA's B tile (W2T, SW128) once
    for (int idx = t; idx < 64 * 16; idx += 256) {
        const int n = idx >> 4, c = (idx & 15) * 4;
        uint4 w4 = *(const uint4*)((const uint32_t*)g_W2T + (kp * MOUT + n) * MHID + c);
        uint32_t byte = ((n >> 3) + (c >> 5) * 8) * 1024 + (n & 7) * 128 + (c & 31) * 4;
        byte ^= (byte >> 3) & 0x70;
        *(uint4*)(P + OFF_B + byte) = w4;
    }
    if (t == 0) {
        asm volatile("mbarrier.init.shared.b64 [%0], 1;" :: "r"(mb_mma) : "memory");
        asm volatile("mbarrier.init.shared.b64 [%0], 1;" :: "r"(mb_free) : "memory");
    }
    if (wid == 0) {
        asm volatile("tcgen05.alloc.cta_group::1.sync.aligned.shared::cta.b32 [%0], %1;"
                     :: "r"(smem_u32(&tmem_ptr_s)), "r"(64u) : "memory");
        asm volatile("tcgen05.relinquish_alloc_permit.cta_group::1.sync.aligned;");
    }
    __syncthreads();
    const uint32_t tmem = tmem_ptr_s;

    if (wid < 4) {
        // ========================= BUILDERS =========================
        // thread constants: col group cg, row base rg; rows rg + 8*it keep
        // r&7 constant so the SW128-swizzled STS address steps by +1024 B.
        const int cg = t & 15;               // column group (4 floats)
        const int rg = (t >> 4) & 7;         // 0..7
        const uint32_t stsoff = ((cg >= 8) ? 16384u : 0u) + (uint32_t)rg * 128u
                              + ((uint32_t)((cg & 7) ^ rg) << 4);
        const float* ubase = g_U + rg * (KT * MHID) + kp * MHID + cg * 4;
        const float* vbase = g_V + kp * MHID + cg * 4;

        int phM = 0, phF = 0, tc = 0;
        for (int tile = tile0; tile < BB * NN; tile += 148, tc++) {
            const int b = tile >> 7, i = tile & 127;

            // prefetch v_i (before any wait)
            const float4 vv = *(const float4*)(vbase + (b * NN + i) * (KT * MHID));

            if (tc > 0) { MBAR_WAIT_PARITY(mb_mma, phM); phM ^= 1; }  // A free
            {
                const float* us = ubase + b * (NN * KT * MHID);
                char* sp = P + OFF_A + stsoff;
#pragma unroll
                for (int it = 0; it < 16; it++, sp += 1024, us += 8 * KT * MHID) {
                    const float4 u = *(const float4*)us;
                    uint4 w4;
                    w4.x = f2tf32(fmaxf(u.x + vv.x, 0.f));
                    w4.y = f2tf32(fmaxf(u.y + vv.y, 0.f));
                    w4.z = f2tf32(fmaxf(u.z + vv.z, 0.f));
                    w4.w = f2tf32(fmaxf(u.w + vv.w, 0.f));
                    *(uint4*)sp = w4;
                }
            }
            asm volatile("bar.sync 1, 128;" ::: "memory");
            if (t == 0) {
                if (tc >= 1) { MBAR_WAIT_PARITY(mb_free, phF); phF ^= 1; }  // TMEM free
                asm volatile("fence.proxy.async.shared::cta;" ::: "memory");
                const uint64_t ad = mk_desc(base + OFF_A);
                const uint64_t bd = mk_desc(base + OFF_B);
#pragma unroll
                for (int s = 0; s < 8; s++)
                    mma_tf32_ss(tmem,
                                ad + ((s >> 2) ? 1024u : 0u) + (s & 3) * 2,
                                bd + ((s >> 2) ? 512u : 0u) + (s & 3) * 2,
                                IDESC_TF32, (uint32_t)(s > 0));
                asm volatile(
                    "tcgen05.commit.cta_group::1.mbarrier::arrive::one.shared::cluster.b64 [%0];"
                    :: "r"(mb_mma) : "memory");
            }
        }
    } else {
        // ========================= EPILOGUE =========================
        const int sub = wid - 4;               // TMEM subpartition
        const int jrow = sub * 32 + lane;      // node j
        int phE = 0, tc = 0;
        for (int tile = tile0; tile < BB * NN; tile += 148, tc++) {
            const int b = tile >> 7, i = tile & 127;

            // rt weight for node j (0 on the diagonal j==i)
            float rt = 0.f;
            if (jrow != i) {
                const int e = i * (NN - 1) + jrow - (jrow > i);
                rt = rel_types[((size_t)b * EDGES + e) * KT + kp];
            }

            MBAR_WAIT_PARITY(mb_mma, phE); phE ^= 1;   // GEMM(tc) done
            asm volatile("tcgen05.fence::after_thread_sync;" ::: "memory");

#pragma unroll
            for (int chv = 0; chv < 2; chv++) {
                float a[32];   // in-place: LDTM output is consumed directly
                LDTM_X32((uint32_t*)a, tmem + chv * 32);
                asm volatile("tcgen05.wait::ld.sync.aligned;" ::: "memory");
#pragma unroll
                for (int c = 0; c < 32; c++)
                    a[c] = rt * fmaxf(a[c] + b2s[chv * 32 + c], 0.f);
                // split-butterfly: lane L ends with col L of this 32-col chunk
#pragma unroll
                for (int o = 16; o >= 1; o >>= 1) {
                    const bool up = (lane & o) != 0;
#pragma unroll
                    for (int c = 0; c < 16; c++) {
                        if (c >= o) break;
                        const float send = up ? a[c] : a[c + o];
                        const float keep = up ? a[c + o] : a[c];
                        a[c] = keep + __shfl_xor_sync(0xFFFFFFFFu, send, o);
                    }
                }
                part[sub][chv * 32 + lane] = a[0];
            }
            asm volatile("tcgen05.fence::before_thread_sync;" ::: "memory");
            asm volatile("bar.sync 2, 128;" ::: "memory");
            if (t == 128)   // TMEM bank free (all epilogue LDTMs done)
                asm volatile("mbarrier.arrive.shared.b64 _, [%0];" :: "r"(mb_free) : "memory");
            {
                const int m = t - 128;
                if (m < 64)
                    g_AGGp[kp][(b * NN + i) * MOUT + m] =
                        part[0][m] + part[1][m] + part[2][m] + part[3][m];
            }
            asm volatile("bar.sync 2, 128;" ::: "memory");
        }
    }

    __syncthreads();
    if (t == 0) {
        asm volatile("mbarrier.inval.shared.b64 [%0];" :: "r"(mb_mma) : "memory");
        asm volatile("mbarrier.inval.shared.b64 [%0];" :: "r"(mb_free) : "memory");
    }
    if (wid == 0)
        asm volatile("tcgen05.dealloc.cta_group::1.sync.aligned.b32 %0, %1;"
                     :: "r"(tmem), "r"(64u));
#else
    // ============ SIMT fallback (compile-only for plain sm_103) ============
    __shared__ float vs0[MHID];
    __shared__ float rts0[NN];
    float* h1  = (float*)P;                  // [128][68]
    float* W2s = (float*)(P + 128 * 68 * 4); // fallback-only layout

    for (int tile = tile0; tile < BB * NN; tile += 148) {
        const int b = tile >> 7, i = tile & 127;
        __syncthreads();
        if (t < 64) vs0[t] = g_V[((b * NN + i) * KT + kp) * MHID + t];
        for (int j = t; j < NN; j += 256) {
            float rt = 0.f;
            if (j != i) {
                const int e = i * (NN - 1) + j - (j > i);
                rt = rel_types[((size_t)b * EDGES + e) * KT + kp];
            }
            rts0[j] = rt;
        }
        __syncthreads();
        for (int idx = t; idx < 128 * 64; idx += 256) {
            const int rr = idx >> 6, h = idx & 63;
            h1[rr * 68 + h] = fmaxf(
                g_U[((b * NN + rr) * KT + kp) * MHID + h] + vs0[h], 0.f);
        }
        for (int idx = t; idx < 64 * 64; idx += 256)
            W2s[idx] = W2[kp * 64 * 64 + idx];
        __syncthreads();
        const int r = t >> 1, cq = (t & 1) * 32;
        float acc[32];
#pragma unroll
        for (int c = 0; c < 32; c++) acc[c] = 0.f;
        for (int kkk = 0; kkk < 64; kkk++) {
            const float a = h1[r * 68 + kkk];
#pragma unroll
            for (int c = 0; c < 32; c++)
                acc[c] = fmaf(a, W2s[kkk * 64 + cq + c], acc[c]);
        }
        const float rt = rts0[r];
        __syncthreads();
        float* red = (float*)P;  // [64 m][stride 132]
#pragma unroll
        for (int c = 0; c < 32; c++)
            red[(cq + c) * 132 + r] = rt * fmaxf(acc[c] + b2s[cq + c], 0.f);
        __syncthreads();
        if (t < 64) {
            float s = 0.f;
            for (int l = 0; l < 128; l++) s += red[t * 132 + l];
            g_AGGp[kp][(b * NN + i) * MOUT + t] = s;
        }
        __syncthreads();
    }
#endif
}

// ---------------------------------------------------------------------------
// Node MLP: grid 64 (64 nodes/CTA), 256 threads, weights staged once.
// ---------------------------------------------------------------------------
__global__ __launch_bounds__(256) void node_kernel(
    const float* __restrict__ inp,
    const float* __restrict__ Wo1, const float* __restrict__ bo1,
    const float* __restrict__ Wo2, const float* __restrict__ bo2,
    const float* __restrict__ Wo3, const float* __restrict__ bo3,
    float* __restrict__ out)
{
    extern __shared__ float nsm[];
    float* sW1 = nsm + NOFF_W1;
    float* sW2 = nsm + NOFF_W2;
    float* sW3 = nsm + NOFF_W3;
    float* sB  = nsm + NOFF_B;
    float* aug = nsm + NOFF_AUG;   // [64][81]
    float* h1  = nsm + NOFF_H1;    // [64][65]
    float* h2  = nsm + NOFF_H2;    // [64][65]

    const int t = threadIdx.x;
    const int b = blockIdx.x >> 1, n0 = (blockIdx.x & 1) * 64;

    for (int idx = t; idx < 80 * 64; idx += 256) sW1[idx] = Wo1[idx];
    for (int idx = t; idx < 64 * 64; idx += 256) sW2[idx] = Wo2[idx];
    for (int idx = t; idx < 64 * 16; idx += 256) sW3[idx] = Wo3[idx];
    if (t < 64) sB[t] = bo1[t];
    if (t < 64) sB[64 + t] = bo2[t];
    if (t < 16) sB[128 + t] = bo3[t];

    {
        const int nn = t >> 2, f0 = (t & 3) * 20;
#pragma unroll
        for (int f = f0; f < f0 + 20; f++) {
            float val;
            if (f < NIN) {
                val = inp[(b * NIN + f) * NN + (n0 + nn)];
            } else {
                const int idx = (b * NN + n0 + nn) * MOUT + (f - NIN);
                val = (g_AGGp[0][idx] + g_AGGp[1][idx]) +
                      (g_AGGp[2][idx] + g_AGGp[3][idx]);
            }
            aug[nn * 81 + f] = val;
        }
    }
    __syncthreads();

    const int nn = t & 63, s = t >> 6;
    {
        float acc[16];
#pragma unroll
        for (int x = 0; x < 16; x++) acc[x] = sB[s * 16 + x];
        for (int f = 0; f < NIN + MOUT; f++) {
            const float a = aug[nn * 81 + f];
#pragma unroll
            for (int x = 0; x < 16; x++)
                acc[x] = fmaf(a, sW1[f * 64 + s * 16 + x], acc[x]);
        }
#pragma unroll
        for (int x = 0; x < 16; x++) h1[nn * 65 + s * 16 + x] = fmaxf(acc[x], 0.f);
    }
    __syncthreads();
    {
        float acc[16];
#pragma unroll
        for (int x = 0; x < 16; x++) acc[x] = sB[64 + s * 16 + x];
        for (int f = 0; f < NHID; f++) {
            const float a = h1[nn * 65 + f];
#pragma unroll
            for (int x = 0; x < 16; x++)
                acc[x] = fmaf(a, sW2[f * 64 + s * 16 + x], acc[x]);
        }
#pragma unroll
        for (int x = 0; x < 16; x++) h2[nn * 65 + s * 16 + x] = fmaxf(acc[x], 0.f);
    }
    __syncthreads();
    {
        float acc[4];
#pragma unroll
        for (int x = 0; x < 4; x++) acc[x] = sB[128 + s * 4 + x];
        for (int f = 0; f < NHID; f++) {
            const float a = h2[nn * 65 + f];
#pragma unroll
            for (int x = 0; x < 4; x++)
                acc[x] = fmaf(a, sW3[f * 16 + s * 4 + x], acc[x]);
        }
#pragma unroll
        for (int x = 0; x < 4; x++)
            out[(b * NOUT + s * 4 + x) * NN + (n0 + nn)] = acc[x];
    }
}

// ---------------------------------------------------------------------------
extern "C" void kernel_launch(void* const* d_in, const int* in_sizes, int n_in,
                              void* d_out, int out_size)
{
    const float* inp       = (const float*)d_in[0];
    const float* rel_types = (const float*)d_in[3];
    const float* W1  = (const float*)d_in[4];
    const float* b1  = (const float*)d_in[5];
    const float* W2  = (const float*)d_in[6];
    const float* b2  = (const float*)d_in[7];
    const float* Wo1 = (const float*)d_in[8];
    const float* bo1 = (const float*)d_in[9];
    const float* Wo2 = (const float*)d_in[10];
    const float* bo2 = (const float*)d_in[11];
    const float* Wo3 = (const float*)d_in[12];
    const float* bo3 = (const float*)d_in[13];
    float* out = (float*)d_out;

    (void)cudaFuncSetAttribute(decoder_kernel,
                               cudaFuncAttributeMaxDynamicSharedMemorySize, DEC_DYN);
    (void)cudaFuncSetAttribute(node_kernel,
                               cudaFuncAttributeMaxDynamicSharedMemorySize, NODE_DYN);

    uv_kernel<<<dim3(8, BB), 256>>>(inp, W1, b1, W2);
    decoder_kernel<<<592, 256, DEC_DYN>>>(rel_types, W2, b2);
    node_kernel<<<64, 256, NODE_DYN>>>(inp, Wo1, bo1, Wo2, bo2, Wo3, bo3, out);
}

// round 15
// speedup vs baseline: 1.3869x; 1.0181x over previous
#include <cuda_runtime.h>
#include <cstdint>

#define BB 32
#define NN 128
#define NIN 16
#define MHID 64
#define MOUT 64
#define NHID 64
#define NOUT 16
#define KT 4
#define EDGES (NN * (NN - 1))

// Scratch (no cudaMalloc allowed)
__device__ float g_U[BB * NN * KT * MHID];    // [b][n][k][h] sender proj
__device__ float g_V[BB * NN * KT * MHID];    // [b][n][k][h] receiver proj + b1
__device__ float g_W2T[KT * MOUT * MHID];     // W2 transposed [k][m][kk], tf32
__device__ float g_AGGp[KT][BB * NN * MOUT];  // per-k partial aggregates

// ---------------- helpers ----------------
__device__ __forceinline__ uint32_t smem_u32(const void* p) {
    uint32_t a;
    asm("{ .reg .u64 t; cvta.to.shared.u64 t, %1; cvt.u32.u64 %0, t; }" : "=r"(a) : "l"(p));
    return a;
}
__device__ __forceinline__ uint32_t f2tf32(float x) {
    uint32_t r; asm("cvt.rna.tf32.f32 %0, %1;" : "=r"(r) : "f"(x)); return r;
}

#if defined(__CUDA_ARCH_FEAT_SM103_ALL)
__device__ __forceinline__ void mma_tf32_ss(uint32_t d, uint64_t a, uint64_t b,
                                            uint32_t idesc, uint32_t en) {
    asm volatile(
        "{\n\t.reg .pred p;\n\tsetp.ne.u32 p, %4, 0;\n\t"
        "tcgen05.mma.cta_group::1.kind::tf32 [%0], %1, %2, %3, {%5, %5, %5, %5}, p;\n\t}\n"
        :: "r"(d), "l"(a), "l"(b), "r"(idesc), "r"(en), "r"(0u) : "memory");
}
#define MBAR_WAIT_PARITY(addr, ph) do {                                          \
    uint32_t _m = (addr), _p = (ph), _done;                                      \
    asm volatile("{\n\t.reg .pred p;\n\t"                                        \
        "mbarrier.try_wait.parity.acquire.cta.shared::cta.b64 p, [%1], %2;\n\t"  \
        "selp.b32 %0, 1, 0, p;\n\t}" : "=r"(_done) : "r"(_m), "r"(_p) : "memory");\
    if (!_done) {                                                                \
        asm volatile("{\n\t.reg .pred P1;\n\t"                                   \
            "WL_%=:\n\t"                                                         \
            "mbarrier.try_wait.parity.acquire.cta.shared::cta.b64 P1, [%0], %1, 0x989680;\n\t" \
            "@P1 bra.uni WD_%=;\n\tbra.uni WL_%=;\n\tWD_%=:\n\t}"                \
            :: "r"(_m), "r"(_p) : "memory");                                     \
    } } while (0)
#define LDTM_X32(r, addr)                                                        \
    asm volatile("tcgen05.ld.sync.aligned.32x32b.x32.b32 "                       \
        "{%0, %1, %2, %3, %4, %5, %6, %7, %8, %9, %10, %11, %12, %13, %14, %15," \
        " %16, %17, %18, %19, %20, %21, %22, %23, %24, %25, %26, %27, %28, %29, %30, %31}, [%32];" \
        : "=r"((r)[0]),  "=r"((r)[1]),  "=r"((r)[2]),  "=r"((r)[3]),             \
          "=r"((r)[4]),  "=r"((r)[5]),  "=r"((r)[6]),  "=r"((r)[7]),             \
          "=r"((r)[8]),  "=r"((r)[9]),  "=r"((r)[10]), "=r"((r)[11]),            \
          "=r"((r)[12]), "=r"((r)[13]), "=r"((r)[14]), "=r"((r)[15]),            \
          "=r"((r)[16]), "=r"((r)[17]), "=r"((r)[18]), "=r"((r)[19]),            \
          "=r"((r)[20]), "=r"((r)[21]), "=r"((r)[22]), "=r"((r)[23]),            \
          "=r"((r)[24]), "=r"((r)[25]), "=r"((r)[26]), "=r"((r)[27]),            \
          "=r"((r)[28]), "=r"((r)[29]), "=r"((r)[30]), "=r"((r)[31])             \
        : "r"(addr))
#define IDESC_TF32 0x08100910u
#define DESC_BASE ((2ull << 61) | (1ull << 46) | (64ull << 32) | (1ull << 16))
__device__ __forceinline__ uint64_t mk_desc(uint32_t addr) {
    return DESC_BASE | ((uint64_t)(addr >> 4) & 0x3FFF);
}
#endif

// decoder dynamic smem layout (from 1024-aligned base); per-CTA (1 edge-type)
#define OFF_B     0          // 16384 (W2T, SW128)
#define OFF_A     16384      // 32768 (h1 tile, SW128)
#define DEC_DYN   (16384 + 32768 + 1024)

// node-MLP kernel smem (float indices)
#define NOFF_W1   0
#define NOFF_W2   5120
#define NOFF_W3   9216
#define NOFF_B    10240
#define NOFF_AUG  10384      // 64*81
#define NOFF_H1   15568      // 64*65
#define NOFF_H2   19728      // 64*65
#define NODE_DYN  (23888 * 4)

// ---------------------------------------------------------------------------
// uv + fused w2t: grid (16, BB), 256 threads, 8 nodes per CTA (low regs).
// ---------------------------------------------------------------------------
__global__ __launch_bounds__(256) void uv_kernel(
    const float* __restrict__ inp, const float* __restrict__ W1,
    const float* __restrict__ b1, const float* __restrict__ W2)
{
    const int g = blockIdx.x, b = blockIdx.y;
    const int n0 = g * 8;
    const int t = threadIdx.x;
    const int k = t >> 6, h = t & 63;

    if (b == 0) {   // fused w2t: 16 groups x 1024 elements = 16384 total
        for (int idx = g * 1024 + t; idx < (g + 1) * 1024; idx += 256) {
            const int kk2 = idx >> 12, rem = idx & 4095, kki = rem >> 6, m = rem & 63;
            ((uint32_t*)g_W2T)[(kk2 * MOUT + m) * MHID + kki] =
                f2tf32(W2[(kk2 * MHID + kki) * MOUT + m]);
        }
    }

    __shared__ float xs[8][NIN];
    if (t < 128) {
        const int nn = t & 7, f = t >> 3;
        xs[nn][f] = inp[(b * NIN + f) * NN + n0 + nn];
    }
    __syncthreads();

    const float* w = W1 + k * (2 * NIN) * MHID;
    const float bv = b1[k * MHID + h];
    float u[8], v[8];
#pragma unroll
    for (int nn = 0; nn < 8; nn++) { u[nn] = 0.f; v[nn] = bv; }
#pragma unroll
    for (int f = 0; f < NIN; f++) {
        const float wu = w[f * MHID + h];
        const float wv = w[(NIN + f) * MHID + h];
#pragma unroll
        for (int nn = 0; nn < 8; nn++) {
            u[nn] = fmaf(xs[nn][f], wu, u[nn]);
            v[nn] = fmaf(xs[nn][f], wv, v[nn]);
        }
    }
#pragma unroll
    for (int nn = 0; nn < 8; nn++) {
        g_U[((b * NN + n0 + nn) * KT + k) * MHID + h] = u[nn];
        g_V[((b * NN + n0 + nn) * KT + k) * MHID + h] = v[nn];
    }
}

// ---------------------------------------------------------------------------
// Persistent k-split decoder: grid 592, 256 threads, 4 CTAs per SM.
// CTA kp = blockIdx.x & 3 owns edge-type kp for every tile.
//   warps 0-3 : branch-free A-build (raw fp32 -> tf32 truncation in-HW) + MMA
//   warps 4-7 : TMEM epilogue (f32x2-packed scale + packed butterfly)
// TMEM: 64 cols per CTA, single buffer (4 x 64 = 256 of 512).
// ---------------------------------------------------------------------------
__global__ __launch_bounds__(256, 4) void decoder_kernel(
    const float* __restrict__ rel_types, const float* __restrict__ W2,
    const float* __restrict__ b2)
{
    extern __shared__ char dsm[];
    __shared__ __align__(8) float b2s[MOUT];
    __shared__ float part[4][MOUT];
    __shared__ uint32_t tmem_ptr_s;
    __shared__ __align__(8) uint64_t mbar[2];  // [0]=mma done, [1]=bank free

    const int t = threadIdx.x;
    const int wid = t >> 5, lane = t & 31;
    const int kp = blockIdx.x & 3;             // edge-type owned by this CTA
    const int tile0 = blockIdx.x >> 2;         // 0..147

    const uint32_t dyn = smem_u32(dsm);
    const uint32_t base = (dyn + 1023) & ~1023u;
    char* P = dsm + (base - dyn);

    if (t < 64) b2s[t] = b2[kp * 64 + t];

#if defined(__CUDA_ARCH_FEAT_SM103_ALL)
    const uint32_t mb_mma  = smem_u32(&mbar[0]);
    const uint32_t mb_free = smem_u32(&mbar[1]);

    // stage this CTA's B tile (W2T, SW128) once
    for (int idx = t; idx < 64 * 16; idx += 256) {
        const int n = idx >> 4, c = (idx & 15) * 4;
        uint4 w4 = *(const uint4*)((const uint32_t*)g_W2T + (kp * MOUT + n) * MHID + c);
        uint32_t byte = ((n >> 3) + (c >> 5) * 8) * 1024 + (n & 7) * 128 + (c & 31) * 4;
        byte ^= (byte >> 3) & 0x70;
        *(uint4*)(P + OFF_B + byte) = w4;
    }
    if (t == 0) {
        asm volatile("mbarrier.init.shared.b64 [%0], 1;" :: "r"(mb_mma) : "memory");
        asm volatile("mbarrier.init.shared.b64 [%0], 1;" :: "r"(mb_free) : "memory");
    }
    if (wid == 0) {
        asm volatile("tcgen05.alloc.cta_group::1.sync.aligned.shared::cta.b32 [%0], %1;"
                     :: "r"(smem_u32(&tmem_ptr_s)), "r"(64u) : "memory");
        asm volatile("tcgen05.relinquish_alloc_permit.cta_group::1.sync.aligned;");
    }
    __syncthreads();
    const uint32_t tmem = tmem_ptr_s;

    if (wid < 4) {
        // ========================= BUILDERS =========================
        const int cg = t & 15;               // column group (4 floats)
        const int rg = (t >> 4) & 7;         // 0..7
        const uint32_t stsoff = ((cg >= 8) ? 16384u : 0u) + (uint32_t)rg * 128u
                              + ((uint32_t)((cg & 7) ^ rg) << 4);
        const float* ubase = g_U + rg * (KT * MHID) + kp * MHID + cg * 4;
        const float* vbase = g_V + kp * MHID + cg * 4;

        int phM = 0, phF = 0, tc = 0;
        for (int tile = tile0; tile < BB * NN; tile += 148, tc++) {
            const int b = tile >> 7, i = tile & 127;

            const float4 vv = *(const float4*)(vbase + (b * NN + i) * (KT * MHID));

            if (tc > 0) { MBAR_WAIT_PARITY(mb_mma, phM); phM ^= 1; }  // A free
            {
                const float* us = ubase + b * (NN * KT * MHID);
                char* sp = P + OFF_A + stsoff;
#pragma unroll
                for (int it = 0; it < 16; it++, sp += 1024, us += 8 * KT * MHID) {
                    const float4 u = *(const float4*)us;
                    uint4 w4;   // raw fp32 — tcgen05 tf32 truncates in-HW
                    w4.x = __float_as_uint(fmaxf(u.x + vv.x, 0.f));
                    w4.y = __float_as_uint(fmaxf(u.y + vv.y, 0.f));
                    w4.z = __float_as_uint(fmaxf(u.z + vv.z, 0.f));
                    w4.w = __float_as_uint(fmaxf(u.w + vv.w, 0.f));
                    *(uint4*)sp = w4;
                }
            }
            asm volatile("bar.sync 1, 128;" ::: "memory");
            if (t == 0) {
                if (tc >= 1) { MBAR_WAIT_PARITY(mb_free, phF); phF ^= 1; }  // TMEM free
                asm volatile("fence.proxy.async.shared::cta;" ::: "memory");
                const uint64_t ad = mk_desc(base + OFF_A);
                const uint64_t bd = mk_desc(base + OFF_B);
#pragma unroll
                for (int s = 0; s < 8; s++)
                    mma_tf32_ss(tmem,
                                ad + ((s >> 2) ? 1024u : 0u) + (s & 3) * 2,
                                bd + ((s >> 2) ? 512u : 0u) + (s & 3) * 2,
                                IDESC_TF32, (uint32_t)(s > 0));
                asm volatile(
                    "tcgen05.commit.cta_group::1.mbarrier::arrive::one.shared::cluster.b64 [%0];"
                    :: "r"(mb_mma) : "memory");
            }
        }
    } else {
        // ========================= EPILOGUE =========================
        const int sub = wid - 4;               // TMEM subpartition
        const int jrow = sub * 32 + lane;      // node j
        int phE = 0, tc = 0;
        for (int tile = tile0; tile < BB * NN; tile += 148, tc++) {
            const int b = tile >> 7, i = tile & 127;

            // rt weight for node j (0 on the diagonal j==i)
            float rt = 0.f;
            if (jrow != i) {
                const int e = i * (NN - 1) + jrow - (jrow > i);
                rt = rel_types[((size_t)b * EDGES + e) * KT + kp];
            }
            unsigned long long rtp;
            asm("mov.b64 %0, {%1, %1};" : "=l"(rtp) : "r"(__float_as_uint(rt)));

            MBAR_WAIT_PARITY(mb_mma, phE); phE ^= 1;   // GEMM(tc) done
            asm volatile("tcgen05.fence::after_thread_sync;" ::: "memory");

#pragma unroll
            for (int chv = 0; chv < 2; chv++) {
                union { float f[32]; unsigned long long u[16]; uint32_t w[32]; } A;
                LDTM_X32(A.w, tmem + chv * 32);
                asm volatile("tcgen05.wait::ld.sync.aligned;" ::: "memory");
                const unsigned long long* b2p =
                    (const unsigned long long*)&b2s[chv * 32];
                // packed +b2
#pragma unroll
                for (int p = 0; p < 16; p++)
                    asm("add.rn.f32x2 %0, %0, %1;" : "+l"(A.u[p]) : "l"(b2p[p]));
                // scalar relu
#pragma unroll
                for (int c = 0; c < 32; c++) A.f[c] = fmaxf(A.f[c], 0.f);
                // packed x rt
#pragma unroll
                for (int p = 0; p < 16; p++)
                    asm("mul.rn.f32x2 %0, %0, %1;" : "+l"(A.u[p]) : "l"(rtp));
                // packed split-butterfly: levels 16..2 on column pairs
#pragma unroll
                for (int o = 16; o >= 2; o >>= 1) {
                    const bool up = (lane & o) != 0;
                    const int hq = o >> 1;
#pragma unroll
                    for (int q = 0; q < 16; q++) {
                        if (q >= hq) break;
                        const unsigned long long send = up ? A.u[q] : A.u[q + hq];
                        unsigned long long keep = up ? A.u[q + hq] : A.u[q];
                        const unsigned long long rs =
                            __shfl_xor_sync(0xFFFFFFFFu, send, o);
                        asm("add.rn.f32x2 %0, %0, %1;" : "+l"(keep) : "l"(rs));
                        A.u[q] = keep;
                    }
                }
                // final level (o=1): a[0], a[1] in the same packed reg
                {
                    const bool up = (lane & 1) != 0;
                    const float send = up ? A.f[0] : A.f[1];
                    const float keep = up ? A.f[1] : A.f[0];
                    part[sub][chv * 32 + lane] =
                        keep + __shfl_xor_sync(0xFFFFFFFFu, send, 1);
                }
            }
            asm volatile("tcgen05.fence::before_thread_sync;" ::: "memory");
            asm volatile("bar.sync 2, 128;" ::: "memory");
            if (t == 128)   // TMEM bank free (all epilogue LDTMs done)
                asm volatile("mbarrier.arrive.shared.b64 _, [%0];" :: "r"(mb_free) : "memory");
            {
                const int m = t - 128;
                if (m < 64)
                    g_AGGp[kp][(b * NN + i) * MOUT + m] =
                        part[0][m] + part[1][m] + part[2][m] + part[3][m];
            }
            asm volatile("bar.sync 2, 128;" ::: "memory");
        }
    }

    __syncthreads();
    if (t == 0) {
        asm volatile("mbarrier.inval.shared.b64 [%0];" :: "r"(mb_mma) : "memory");
        asm volatile("mbarrier.inval.shared.b64 [%0];" :: "r"(mb_free) : "memory");
    }
    if (wid == 0)
        asm volatile("tcgen05.dealloc.cta_group::1.sync.aligned.b32 %0, %1;"
                     :: "r"(tmem), "r"(64u));
#else
    // ============ SIMT fallback (compile-only for plain sm_103) ============
    __shared__ float vs0[MHID];
    __shared__ float rts0[NN];
    float* h1  = (float*)P;                  // [128][68]
    float* W2s = (float*)(P + 128 * 68 * 4); // fallback-only layout

    for (int tile = tile0; tile < BB * NN; tile += 148) {
        const int b = tile >> 7, i = tile & 127;
        __syncthreads();
        if (t < 64) vs0[t] = g_V[((b * NN + i) * KT + kp) * MHID + t];
        for (int j = t; j < NN; j += 256) {
            float rt = 0.f;
            if (j != i) {
                const int e = i * (NN - 1) + j - (j > i);
                rt = rel_types[((size_t)b * EDGES + e) * KT + kp];
            }
            rts0[j] = rt;
        }
        __syncthreads();
        for (int idx = t; idx < 128 * 64; idx += 256) {
            const int rr = idx >> 6, h = idx & 63;
            h1[rr * 68 + h] = fmaxf(
                g_U[((b * NN + rr) * KT + kp) * MHID + h] + vs0[h], 0.f);
        }
        for (int idx = t; idx < 64 * 64; idx += 256)
            W2s[idx] = W2[kp * 64 * 64 + idx];
        __syncthreads();
        const int r = t >> 1, cq = (t & 1) * 32;
        float acc[32];
#pragma unroll
        for (int c = 0; c < 32; c++) acc[c] = 0.f;
        for (int kkk = 0; kkk < 64; kkk++) {
            const float a = h1[r * 68 + kkk];
#pragma unroll
            for (int c = 0; c < 32; c++)
                acc[c] = fmaf(a, W2s[kkk * 64 + cq + c], acc[c]);
        }
        const float rt = rts0[r];
        __syncthreads();
        float* red = (float*)P;  // [64 m][stride 132]
#pragma unroll
        for (int c = 0; c < 32; c++)
            red[(cq + c) * 132 + r] = rt * fmaxf(acc[c] + b2s[cq + c], 0.f);
        __syncthreads();
        if (t < 64) {
            float s = 0.f;
            for (int l = 0; l < 128; l++) s += red[t * 132 + l];
            g_AGGp[kp][(b * NN + i) * MOUT + t] = s;
        }
        __syncthreads();
    }
#endif
}

// ---------------------------------------------------------------------------
// Node MLP: grid 64 (64 nodes/CTA), 256 threads, weights staged once.
// ---------------------------------------------------------------------------
__global__ __launch_bounds__(256) void node_kernel(
    const float* __restrict__ inp,
    const float* __restrict__ Wo1, const float* __restrict__ bo1,
    const float* __restrict__ Wo2, const float* __restrict__ bo2,
    const float* __restrict__ Wo3, const float* __restrict__ bo3,
    float* __restrict__ out)
{
    extern __shared__ float nsm[];
    float* sW1 = nsm + NOFF_W1;
    float* sW2 = nsm + NOFF_W2;
    float* sW3 = nsm + NOFF_W3;
    float* sB  = nsm + NOFF_B;
    float* aug = nsm + NOFF_AUG;   // [64][81]
    float* h1  = nsm + NOFF_H1;    // [64][65]
    float* h2  = nsm + NOFF_H2;    // [64][65]

    const int t = threadIdx.x;
    const int b = blockIdx.x >> 1, n0 = (blockIdx.x & 1) * 64;

    for (int idx = t; idx < 80 * 64; idx += 256) sW1[idx] = Wo1[idx];
    for (int idx = t; idx < 64 * 64; idx += 256) sW2[idx] = Wo2[idx];
    for (int idx = t; idx < 64 * 16; idx += 256) sW3[idx] = Wo3[idx];
    if (t < 64) sB[t] = bo1[t];
    if (t < 64) sB[64 + t] = bo2[t];
    if (t < 16) sB[128 + t] = bo3[t];

    {
        const int nn = t >> 2, f0 = (t & 3) * 20;
#pragma unroll
        for (int f = f0; f < f0 + 20; f++) {
            float val;
            if (f < NIN) {
                val = inp[(b * NIN + f) * NN + (n0 + nn)];
            } else {
                const int idx = (b * NN + n0 + nn) * MOUT + (f - NIN);
                val = (g_AGGp[0][idx] + g_AGGp[1][idx]) +
                      (g_AGGp[2][idx] + g_AGGp[3][idx]);
            }
            aug[nn * 81 + f] = val;
        }
    }
    __syncthreads();

    const int nn = t & 63, s = t >> 6;
    {
        float acc[16];
#pragma unroll
        for (int x = 0; x < 16; x++) acc[x] = sB[s * 16 + x];
        for (int f = 0; f < NIN + MOUT; f++) {
            const float a = aug[nn * 81 + f];
#pragma unroll
            for (int x = 0; x < 16; x++)
                acc[x] = fmaf(a, sW1[f * 64 + s * 16 + x], acc[x]);
        }
#pragma unroll
        for (int x = 0; x < 16; x++) h1[nn * 65 + s * 16 + x] = fmaxf(acc[x], 0.f);
    }
    __syncthreads();
    {
        float acc[16];
#pragma unroll
        for (int x = 0; x < 16; x++) acc[x] = sB[64 + s * 16 + x];
        for (int f = 0; f < NHID; f++) {
            const float a = h1[nn * 65 + f];
#pragma unroll
            for (int x = 0; x < 16; x++)
                acc[x] = fmaf(a, sW2[f * 64 + s * 16 + x], acc[x]);
        }
#pragma unroll
        for (int x = 0; x < 16; x++) h2[nn * 65 + s * 16 + x] = fmaxf(acc[x], 0.f);
    }
    __syncthreads();
    {
        float acc[4];
#pragma unroll
        for (int x = 0; x < 4; x++) acc[x] = sB[128 + s * 4 + x];
        for (int f = 0; f < NHID; f++) {
            const float a = h2[nn * 65 + f];
#pragma unroll
            for (int x = 0; x < 4; x++)
                acc[x] = fmaf(a, sW3[f * 16 + s * 4 + x], acc[x]);
        }
#pragma unroll
        for (int x = 0; x < 4; x++)
            out[(b * NOUT + s * 4 + x) * NN + (n0 + nn)] = acc[x];
    }
}

// ---------------------------------------------------------------------------
extern "C" void kernel_launch(void* const* d_in, const int* in_sizes, int n_in,
                              void* d_out, int out_size)
{
    const float* inp       = (const float*)d_in[0];
    const float* rel_types = (const float*)d_in[3];
    const float* W1  = (const float*)d_in[4];
    const float* b1  = (const float*)d_in[5];
    const float* W2  = (const float*)d_in[6];
    const float* b2  = (const float*)d_in[7];
    const float* Wo1 = (const float*)d_in[8];
    const float* bo1 = (const float*)d_in[9];
    const float* Wo2 = (const float*)d_in[10];
    const float* bo2 = (const float*)d_in[11];
    const float* Wo3 = (const float*)d_in[12];
    const float* bo3 = (const float*)d_in[13];
    float* out = (float*)d_out;

    (void)cudaFuncSetAttribute(decoder_kernel,
                               cudaFuncAttributeMaxDynamicSharedMemorySize, DEC_DYN);
    (void)cudaFuncSetAttribute(node_kernel,
                               cudaFuncAttributeMaxDynamicSharedMemorySize, NODE_DYN);

    uv_kernel<<<dim3(16, BB), 256>>>(inp, W1, b1, W2);
    decoder_kernel<<<592, 256, DEC_DYN>>>(rel_types, W2, b2);
    node_kernel<<<64, 256, NODE_DYN>>>(inp, Wo1, bo1, Wo2, bo2, Wo3, bo3, out);
}